// round 14
// baseline (speedup 1.0000x reference)
#include <cuda_runtime.h>
#include <cuda_bf16.h>
#include <math.h>
#include <stdint.h>

#define DD 1024
#define NB 8
#define NS 64
#define NM 4096
#define EPS_F 1e-6f
#define SCALE_F 0.03125f

// ---------------------------------------------------------------------------
// Scratch (static device globals)
// ---------------------------------------------------------------------------
__device__ __nv_bfloat16 g_pnh[(long)NB*NM*DD], g_pnl[(long)NB*NM*DD];   // rmsnormed P [bm][d]
__device__ __nv_bfloat16 g_pth[(long)NB*NM*DD], g_ptl[(long)NB*NM*DD];   // PnT [d][b*4096+m]
__device__ __nv_bfloat16 g_wqh[DD*DD],  g_wql[DD*DD];
__device__ __nv_bfloat16 g_wkh[DD*DD],  g_wkl[DD*DD];
__device__ __nv_bfloat16 g_wvh[DD*DD],  g_wvl[DD*DD];
__device__ __nv_bfloat16 g_wqth[DD*DD], g_wqtl[DD*DD];    // WqT
__device__ __nv_bfloat16 g_wkth[DD*DD], g_wktl[DD*DD];    // WkT
__device__ __nv_bfloat16 g_wqkth[DD*DD], g_wqktl[DD*DD];  // (Wq^T Wk)^T
__device__ __nv_bfloat16 g_wbh[2L*3*DD*DD], g_wbl[2L*3*DD*DD];    // gates B: [0]=wih, [1]=whh
__device__ __nv_bfloat16 g_ush[2L*NB*NS*DD], g_usl[2L*NB*NS*DD];  // gates A: [0]=u, [1]=slots raw
__device__ __nv_bfloat16 g_awh[NB*NS*DD], g_awl[NB*NS*DD];        // aw = attn @ Pn (renormed)
__device__ float g_gcat[2L*NB*NS*3*DD];                           // [0]=gx [1]=gh
__device__ float g_bias2[2*3*DD];
__device__ float g_slots[NB*NS*DD];
__device__ __nv_bfloat16 g_snh[NB*NS*DD], g_snl[NB*NS*DD];        // normed slots hi/lo
__device__ __nv_bfloat16 g_qkh[NB*NS*DD], g_qkl[NB*NS*DD];
__device__ float g_part[NB*32*64];
__device__ float g_cpart[32L*DD*NS];                              // split-K partials (8MB)
__device__ __nv_bfloat16 g_ath[(long)NB*NS*NM], g_atl[(long)NB*NS*NM];  // p (softmaxed) [b][k][m]

#define U_OFF  ((long)NB*NS*DD)
#define W_OFF  (3L*DD*DD)
#define G_OFF  ((long)NB*NS*3*DD)

// ---------------------------------------------------------------------------
// Helpers
// ---------------------------------------------------------------------------
__device__ __forceinline__ uint32_t smem_u32(const void* p) {
    uint32_t a;
    asm("{ .reg .u64 t; cvta.to.shared.u64 t, %1; cvt.u32.u64 %0, t; }" : "=r"(a) : "l"(p));
    return a;
}
__device__ __forceinline__ void cpa16(uint32_t dst, const void* src) {
    asm volatile("cp.async.cg.shared.global [%0], [%1], 16;" :: "r"(dst), "l"(src) : "memory");
}
#define CP_COMMIT() asm volatile("cp.async.commit_group;" ::: "memory")
#define CP_WAIT2()  asm volatile("cp.async.wait_group 2;" ::: "memory")
#define CP_WAIT0()  asm volatile("cp.async.wait_group 0;" ::: "memory")

#define LDSM4(r, addr) \
    asm volatile("ldmatrix.sync.aligned.m8n8.x4.shared.b16 {%0,%1,%2,%3}, [%4];" \
        : "=r"((r)[0]), "=r"((r)[1]), "=r"((r)[2]), "=r"((r)[3]) : "r"(addr))

#define MMA4(d, a, b0, b1) \
    asm volatile("mma.sync.aligned.m16n8k16.row.col.f32.bf16.bf16.f32 " \
        "{%0,%1,%2,%3},{%4,%5,%6,%7},{%8,%9},{%0,%1,%2,%3};" \
        : "+f"((d)[0]), "+f"((d)[1]), "+f"((d)[2]), "+f"((d)[3]) \
        : "r"((a)[0]), "r"((a)[1]), "r"((a)[2]), "r"((a)[3]), "r"(b0), "r"(b1))

__device__ __forceinline__ uint32_t pack2(float a, float b) {
    __nv_bfloat162 t = __floats2bfloat162_rn(a, b);
    return *reinterpret_cast<uint32_t*>(&t);
}
__device__ __forceinline__ void d2(float v, float& hi, float& lo) {
    __nv_bfloat16 h = __float2bfloat16_rn(v);
    hi = __bfloat162float(h);
    lo = v - hi;
}

// ---------------------------------------------------------------------------
// Prefetch one BK=32 chunk of A(BM rows) + B(TN rows), hi & lo, into a stage.
// ---------------------------------------------------------------------------
template <int BM, int TN>
__device__ __forceinline__ void prefetch_tiles(
    uint32_t stage,
    const __nv_bfloat16* __restrict__ Ah, const __nv_bfloat16* __restrict__ Al,
    const __nv_bfloat16* __restrict__ Bh, const __nv_bfloat16* __restrict__ Bl,
    long lda, long ldb, int m0, int n0, int k0, int tid)
{
    constexpr int AL_OFF = BM * 80;
    constexpr int BH_OFF = 2 * BM * 80;
#pragma unroll
    for (int i = 0; i < BM / 64; i++) {
        int idx = tid + i * 256;
        int r = idx >> 2, ch = idx & 3;
        long g = (long)(m0 + r) * lda + k0 + ch * 8;
        uint32_t d = stage + (uint32_t)(r * 80 + ch * 16);
        cpa16(d, Ah + g);
        cpa16(d + AL_OFF, Al + g);
    }
#pragma unroll
    for (int i = 0; i < TN / 64; i++) {
        int idx = tid + i * 256;
        int r = idx >> 2, ch = idx & 3;
        long g = (long)(n0 + r) * ldb + k0 + ch * 8;
        uint32_t d = stage + BH_OFF + (uint32_t)(r * 80 + ch * 16);
        cpa16(d, Bh + g);
        cpa16(d + TN * 80, Bl + g);
    }
}

// ---------------------------------------------------------------------------
// bf16x3 NT GEMM via mma.sync, 3-stage cp.async pipeline, 8 warps, 2 CTAs/SM.
// Split-K: blockIdx.z = zb*nsplit + zk.
// EPI: 0 = fp32 out (alpha, bias)   C[m][n]
//      1 = bf16 hi/lo out           C[m][n]
//      3 = softmax over n (TN=64, BM=128, grid.x==1), then bf16 hi/lo
//          TRANSPOSED store Ct[n][m] (un-renormalized) + column partials
// ---------------------------------------------------------------------------
template <int BM, int TN, int EPI>
__global__ __launch_bounds__(256, 2)
void mma_nt(const __nv_bfloat16* __restrict__ Ah, const __nv_bfloat16* __restrict__ Al,
            long lda, long sA,
            const __nv_bfloat16* __restrict__ Bh, const __nv_bfloat16* __restrict__ Bl,
            long ldb, long sB,
            float* __restrict__ Cf,
            __nv_bfloat16* __restrict__ Ch, __nv_bfloat16* __restrict__ Cl,
            long ldc, long sC,
            int Kd, const float* __restrict__ bias, long sBias, float alpha,
            int nsplit, long sAk, long sBk, float* __restrict__ part)
{
    constexpr int WMW = BM / 32;
    constexpr int WNW = 8 / WMW;
    constexpr int WN = TN / WNW;
    constexpr int NF = WN / 8;
    constexpr int NF16 = WN / 16;
    constexpr int AL_OFF = BM * 80;
    constexpr int BH_OFF = 2 * BM * 80;
    constexpr int STAGE = (BM + TN) * 160;

    extern __shared__ char smem[];
    const uint32_t sb = smem_u32(smem);
    const int tid = threadIdx.x, lane = tid & 31, wid = tid >> 5;
    const int wm = wid % WMW, wn = wid / WMW;

    const int m0 = blockIdx.y * BM, n0 = blockIdx.x * TN;
    int zb = blockIdx.z, zk = 0;
    if (nsplit > 1) { zb = blockIdx.z / nsplit; zk = blockIdx.z % nsplit; }
    Ah += (long)zb * sA + (long)zk * sAk;  Al += (long)zb * sA + (long)zk * sAk;
    Bh += (long)zb * sB + (long)zk * sBk;  Bl += (long)zb * sB + (long)zk * sBk;
    if (bias) bias += (long)zb * sBias;

    float acc[2][NF][4];
#pragma unroll
    for (int i = 0; i < 2; i++)
#pragma unroll
        for (int j = 0; j < NF; j++)
#pragma unroll
            for (int k = 0; k < 4; k++) acc[i][j][k] = 0.f;

    const uint32_t aoff = (uint32_t)((wm * 32 + (lane & 15)) * 80 + (lane >> 4) * 16);
    const uint32_t boff = (uint32_t)(BH_OFF + (wn * WN + (lane & 15)) * 80 + (lane >> 4) * 16);

    const int NC = Kd >> 5;
    prefetch_tiles<BM, TN>(sb,             Ah, Al, Bh, Bl, lda, ldb, m0, n0, 0,  tid);
    CP_COMMIT();
    prefetch_tiles<BM, TN>(sb + STAGE,     Ah, Al, Bh, Bl, lda, ldb, m0, n0, 32, tid);
    CP_COMMIT();
    prefetch_tiles<BM, TN>(sb + 2 * STAGE, Ah, Al, Bh, Bl, lda, ldb, m0, n0, 64, tid);
    CP_COMMIT();

    int sidx = 0;
    for (int c = 0; c < NC; c++) {
        CP_WAIT2();
        __syncthreads();
        const uint32_t st = sb + sidx * STAGE;
#pragma unroll
        for (int ks = 0; ks < 2; ks++) {
            const uint32_t ka = st + aoff + ks * 32;
            const uint32_t kb = st + boff + ks * 32;
            uint32_t ah[2][4], al[2][4];
            LDSM4(ah[0], ka);
            LDSM4(ah[1], ka + 16 * 80);
            LDSM4(al[0], ka + AL_OFF);
            LDSM4(al[1], ka + AL_OFF + 16 * 80);
            uint32_t bh[NF16][4], bl[NF16][4];
#pragma unroll
            for (int nf = 0; nf < NF16; nf++) {
                LDSM4(bh[nf], kb + nf * 16 * 80);
                LDSM4(bl[nf], kb + TN * 80 + nf * 16 * 80);
            }
#pragma unroll
            for (int mf = 0; mf < 2; mf++)
#pragma unroll
                for (int nf = 0; nf < NF16; nf++) {
                    MMA4(acc[mf][2*nf],   ah[mf], bh[nf][0], bh[nf][2]);
                    MMA4(acc[mf][2*nf+1], ah[mf], bh[nf][1], bh[nf][3]);
                    MMA4(acc[mf][2*nf],   ah[mf], bl[nf][0], bl[nf][2]);
                    MMA4(acc[mf][2*nf+1], ah[mf], bl[nf][1], bl[nf][3]);
                    MMA4(acc[mf][2*nf],   al[mf], bh[nf][0], bh[nf][2]);
                    MMA4(acc[mf][2*nf+1], al[mf], bh[nf][1], bh[nf][3]);
                }
        }
        __syncthreads();
        if (c + 3 < NC)
            prefetch_tiles<BM, TN>(sb + sidx * STAGE, Ah, Al, Bh, Bl,
                                   lda, ldb, m0, n0, (c + 3) * 32, tid);
        CP_COMMIT();
        sidx = (sidx == 2) ? 0 : sidx + 1;
    }
    CP_WAIT0();
    __syncthreads();

    // ---- epilogue ----
    const int rbase = m0 + wm * 32;
    const int cbase = n0 + wn * WN;
    if (EPI == 0) {
        float* C = Cf + (long)blockIdx.z * sC;
#pragma unroll
        for (int mf = 0; mf < 2; mf++) {
            int row = rbase + mf * 16 + (lane >> 2);
#pragma unroll
            for (int nf = 0; nf < NF; nf++) {
                int col = cbase + nf * 8 + (lane & 3) * 2;
                float b0 = bias ? bias[col] : 0.f, b1 = bias ? bias[col + 1] : 0.f;
                float2 v0 = make_float2(acc[mf][nf][0] * alpha + b0,
                                        acc[mf][nf][1] * alpha + b1);
                float2 v1 = make_float2(acc[mf][nf][2] * alpha + b0,
                                        acc[mf][nf][3] * alpha + b1);
                *(float2*)(C + (long)row * ldc + col) = v0;
                *(float2*)(C + (long)(row + 8) * ldc + col) = v1;
            }
        }
    } else if (EPI == 1) {
        __nv_bfloat16* CH = Ch + (long)blockIdx.z * sC;
        __nv_bfloat16* CL = Cl + (long)blockIdx.z * sC;
#pragma unroll
        for (int mf = 0; mf < 2; mf++) {
            int row = rbase + mf * 16 + (lane >> 2);
#pragma unroll
            for (int nf = 0; nf < NF; nf++) {
                int col = cbase + nf * 8 + (lane & 3) * 2;
                float h0, l0, h1, l1;
                d2(acc[mf][nf][0] * alpha, h0, l0);
                d2(acc[mf][nf][1] * alpha, h1, l1);
                *(uint32_t*)(CH + (long)row * ldc + col) = pack2(h0, h1);
                *(uint32_t*)(CL + (long)row * ldc + col) = pack2(l0, l1);
                d2(acc[mf][nf][2] * alpha, h0, l0);
                d2(acc[mf][nf][3] * alpha, h1, l1);
                *(uint32_t*)(CH + (long)(row + 8) * ldc + col) = pack2(h0, h1);
                *(uint32_t*)(CL + (long)(row + 8) * ldc + col) = pack2(l0, l1);
            }
        }
    } else {
        // EPI==3: in-CTA softmax over full n (TN==NS), bf16 hi/lo transposed
        // store (un-renormalized) + per-block column partial sums.
        float* ts = reinterpret_cast<float*>(smem);
        const int rl = wm * 32;
        const int cl = wn * WN;
#pragma unroll
        for (int mf = 0; mf < 2; mf++) {
            int row = rl + mf * 16 + (lane >> 2);
#pragma unroll
            for (int nf = 0; nf < NF; nf++) {
                int col = cl + nf * 8 + (lane & 3) * 2;
                ts[(row)     * 65 + col]     = acc[mf][nf][0] * alpha;
                ts[(row)     * 65 + col + 1] = acc[mf][nf][1] * alpha;
                ts[(row + 8) * 65 + col]     = acc[mf][nf][2] * alpha;
                ts[(row + 8) * 65 + col + 1] = acc[mf][nf][3] * alpha;
            }
        }
        __syncthreads();
        {
            int row = tid >> 1, half = tid & 1;
            float* p = ts + row * 65 + half * 32;
            float mx = -INFINITY;
#pragma unroll
            for (int i = 0; i < 32; i++) mx = fmaxf(mx, p[i]);
            mx = fmaxf(mx, __shfl_xor_sync(0xffffffffu, mx, 1));
            float sum = 0.f;
            float e[32];
#pragma unroll
            for (int i = 0; i < 32; i++) { e[i] = __expf(p[i] - mx); sum += e[i]; }
            sum += __shfl_xor_sync(0xffffffffu, sum, 1);
            float inv = 1.f / sum;
#pragma unroll
            for (int i = 0; i < 32; i++) p[i] = e[i] * inv;
        }
        __syncthreads();
        if (tid < 64) {
            float s = 0.f;
#pragma unroll 8
            for (int r = 0; r < 128; r++) s += ts[r * 65 + tid];
            part[((long)blockIdx.z * gridDim.y + blockIdx.y) * 64 + tid] = s;
        }
#pragma unroll
        for (int j = 0; j < 16; j++) {
            int u = tid + j * 256;
            int k = u >> 6, m2 = (u & 63) * 2;
            float v0 = ts[(m2 + 0) * 65 + k];
            float v1 = ts[(m2 + 1) * 65 + k];
            float h0, l0, h1, l1;
            d2(v0, h0, l0); d2(v1, h1, l1);
            long o = ((long)blockIdx.z * 64 + k) * NM + m0 + m2;
            *(uint32_t*)(Ch + o) = pack2(h0, h1);
            *(uint32_t*)(Cl + o) = pack2(l0, l1);
        }
    }
}

// ---------------------------------------------------------------------------
// Elementwise / layout kernels
// ---------------------------------------------------------------------------
// fused rms + scale + decomp + dual-layout (Pn, PnT). One block per 64 m-rows.
__global__ void rms_scale_tr(const float* __restrict__ P, const float* __restrict__ w,
                             __nv_bfloat16* __restrict__ H, __nv_bfloat16* __restrict__ L,
                             __nv_bfloat16* __restrict__ HT, __nv_bfloat16* __restrict__ LT,
                             long R) {
    __shared__ float rs[64];
    __shared__ uint16_t th[64][66], tl[64][66];
    long m0 = (long)blockIdx.x * 64;
    int tid = threadIdx.x;

    // phase A: row rms (4 threads per row)
    {
        int row = tid >> 2, q = tid & 3;
        const float4* pr = (const float4*)(P + (m0 + row) * DD) + q * 64;
        float s = 0.f;
#pragma unroll 8
        for (int i = 0; i < 64; i++) {
            float4 v = pr[i];
            s += v.x * v.x + v.y * v.y + v.z * v.z + v.w * v.w;
        }
        s += __shfl_xor_sync(0xffffffffu, s, 1);
        s += __shfl_xor_sync(0xffffffffu, s, 2);
        if (q == 0) rs[row] = rsqrtf(s * (1.f / DD) + EPS_F);
    }
    __syncthreads();

    // phase B: 16 subtiles of 64m x 64d (P re-read is L2-hot)
    for (int sub = 0; sub < 16; sub++) {
        int d0 = sub * 64;
#pragma unroll
        for (int j = 0; j < 4; j++) {
            int u = tid + j * 256;
            int row = u >> 4, c4 = (u & 15) * 4;
            long gi = (m0 + row) * DD + d0 + c4;
            float4 v = *(const float4*)(P + gi);
            float rsv = rs[row];
            float h0, h1, h2, h3, l0, l1, l2, l3;
            d2(v.x * rsv * w[d0 + c4 + 0], h0, l0);
            d2(v.y * rsv * w[d0 + c4 + 1], h1, l1);
            d2(v.z * rsv * w[d0 + c4 + 2], h2, l2);
            d2(v.w * rsv * w[d0 + c4 + 3], h3, l3);
            *(uint2*)(H + gi) = make_uint2(pack2(h0, h1), pack2(h2, h3));
            *(uint2*)(L + gi) = make_uint2(pack2(l0, l1), pack2(l2, l3));
            uint16_t* hp = (uint16_t*)&th[row][c4];
            uint16_t* lp = (uint16_t*)&tl[row][c4];
            __nv_bfloat16 b;
            b = __float2bfloat16_rn(h0); hp[0] = *(uint16_t*)&b;
            b = __float2bfloat16_rn(h1); hp[1] = *(uint16_t*)&b;
            b = __float2bfloat16_rn(h2); hp[2] = *(uint16_t*)&b;
            b = __float2bfloat16_rn(h3); hp[3] = *(uint16_t*)&b;
            b = __float2bfloat16_rn(l0); lp[0] = *(uint16_t*)&b;
            b = __float2bfloat16_rn(l1); lp[1] = *(uint16_t*)&b;
            b = __float2bfloat16_rn(l2); lp[2] = *(uint16_t*)&b;
            b = __float2bfloat16_rn(l3); lp[3] = *(uint16_t*)&b;
        }
        __syncthreads();
#pragma unroll
        for (int j = 0; j < 8; j++) {
            int u = tid + j * 256;
            int d = u >> 5, m2 = (u & 31) * 2;
            uint32_t vh = (uint32_t)th[m2][d] | ((uint32_t)th[m2 + 1][d] << 16);
            uint32_t vl = (uint32_t)tl[m2][d] | ((uint32_t)tl[m2 + 1][d] << 16);
            long o = (long)(d0 + d) * R + m0 + m2;
            *(uint32_t*)(HT + o) = vh;
            *(uint32_t*)(LT + o) = vl;
        }
        __syncthreads();
    }
}

__global__ void rmsdecomp(const float* __restrict__ X,
                          __nv_bfloat16* __restrict__ H, __nv_bfloat16* __restrict__ L,
                          const float* __restrict__ w) {
    long r = blockIdx.x;
    float4 v = ((const float4*)(X + r * DD))[threadIdx.x];
    float s = v.x * v.x + v.y * v.y + v.z * v.z + v.w * v.w;
    for (int o = 16; o; o >>= 1) s += __shfl_xor_sync(0xffffffffu, s, o);
    __shared__ float red[8];
    __shared__ float srs;
    if ((threadIdx.x & 31) == 0) red[threadIdx.x >> 5] = s;
    __syncthreads();
    if (threadIdx.x == 0) {
        float t = 0.f;
#pragma unroll
        for (int i = 0; i < 8; i++) t += red[i];
        srs = rsqrtf(t * (1.f / DD) + EPS_F);
    }
    __syncthreads();
    float rs = srs;
    float4 ww = ((const float4*)w)[threadIdx.x];
    float h0, h1, h2, h3, l0, l1, l2, l3;
    d2(v.x * rs * ww.x, h0, l0); d2(v.y * rs * ww.y, h1, l1);
    d2(v.z * rs * ww.z, h2, l2); d2(v.w * rs * ww.w, h3, l3);
    ((uint2*)H)[r * 256 + threadIdx.x] = make_uint2(pack2(h0, h1), pack2(h2, h3));
    ((uint2*)L)[r * 256 + threadIdx.x] = make_uint2(pack2(l0, l1), pack2(l2, l3));
}

// batched hi/lo decomposition over 5 weight tensors (one launch)
__global__ void decomp5(const float* __restrict__ s0, __nv_bfloat16* d0h, __nv_bfloat16* d0l, long n0,
                        const float* __restrict__ s1, __nv_bfloat16* d1h, __nv_bfloat16* d1l, long n1,
                        const float* __restrict__ s2, __nv_bfloat16* d2h_, __nv_bfloat16* d2l, long n2,
                        const float* __restrict__ s3, __nv_bfloat16* d3h, __nv_bfloat16* d3l, long n3,
                        const float* __restrict__ s4, __nv_bfloat16* d4h, __nv_bfloat16* d4l, long n4c) {
    long i = (long)blockIdx.x * blockDim.x + threadIdx.x;
    const float* src; __nv_bfloat16 *dh, *dl;
    if (i < n0)      { src = s0; dh = d0h; dl = d0l; }
    else if ((i -= n0) < n1) { src = s1; dh = d1h; dl = d1l; }
    else if ((i -= n1) < n2) { src = s2; dh = d2h_; dl = d2l; }
    else if ((i -= n2) < n3) { src = s3; dh = d3h; dl = d3l; }
    else if ((i -= n3) < n4c) { src = s4; dh = d4h; dl = d4l; }
    else return;
    float4 v = ((const float4*)src)[i];
    float h0, h1, h2, h3, l0, l1, l2, l3;
    d2(v.x, h0, l0); d2(v.y, h1, l1); d2(v.z, h2, l2); d2(v.w, h3, l3);
    ((uint2*)dh)[i] = make_uint2(pack2(h0, h1), pack2(h2, h3));
    ((uint2*)dl)[i] = make_uint2(pack2(l0, l1), pack2(l2, l3));
}

__global__ void decomp4(const float* __restrict__ X,
                        __nv_bfloat16* __restrict__ H, __nv_bfloat16* __restrict__ L,
                        long n4) {
    long i = (long)blockIdx.x * blockDim.x + threadIdx.x;
    if (i >= n4) return;
    float4 v = ((const float4*)X)[i];
    float h0, h1, h2, h3, l0, l1, l2, l3;
    d2(v.x, h0, l0); d2(v.y, h1, l1); d2(v.z, h2, l2); d2(v.w, h3, l3);
    ((uint2*)H)[i] = make_uint2(pack2(h0, h1), pack2(h2, h3));
    ((uint2*)L)[i] = make_uint2(pack2(l0, l1), pack2(l2, l3));
}

// sum 2 split-K fp32 slices, decompose hi/lo
__global__ void sum2_dec(const float* __restrict__ cp,
                         __nv_bfloat16* __restrict__ H, __nv_bfloat16* __restrict__ L,
                         long n4) {
    long i = (long)blockIdx.x * blockDim.x + threadIdx.x;
    if (i >= n4) return;
    float4 a = ((const float4*)cp)[i];
    float4 b = ((const float4*)cp)[i + n4];
    a.x += b.x; a.y += b.y; a.z += b.z; a.w += b.w;
    float h0, h1, h2, h3, l0, l1, l2, l3;
    d2(a.x, h0, l0); d2(a.y, h1, l1); d2(a.z, h2, l2); d2(a.w, h3, l3);
    ((uint2*)H)[i] = make_uint2(pack2(h0, h1), pack2(h2, h3));
    ((uint2*)L)[i] = make_uint2(pack2(l0, l1), pack2(l2, l3));
}

// 64x64-tile transpose of a bf16 hi/lo pair: [R][C] -> [C][R]
__global__ void trans_pair(const __nv_bfloat16* __restrict__ H, const __nv_bfloat16* __restrict__ L,
                           __nv_bfloat16* __restrict__ HT, __nv_bfloat16* __restrict__ LT,
                           int C, long R) {
    __shared__ uint16_t t[64][66];
    long r0 = (long)blockIdx.y * 64;
    int c0 = blockIdx.x * 64;
    int tid = threadIdx.x;
#pragma unroll
    for (int pass = 0; pass < 2; pass++) {
        const __nv_bfloat16* src = pass ? L : H;
        __nv_bfloat16* dst = pass ? LT : HT;
#pragma unroll
        for (int j = 0; j < 8; j++) {
            int u = tid + j * 256;
            int r = u >> 5, c2 = (u & 31) * 2;
            uint32_t v = *(const uint32_t*)(src + (r0 + r) * C + c0 + c2);
            t[r][c2] = (uint16_t)(v & 0xffff);
            t[r][c2 + 1] = (uint16_t)(v >> 16);
        }
        __syncthreads();
#pragma unroll
        for (int j = 0; j < 8; j++) {
            int u = tid + j * 256;
            int c = u >> 5, r2 = (u & 31) * 2;
            uint32_t v = (uint32_t)t[r2][c] | ((uint32_t)t[r2 + 1][c] << 16);
            *(uint32_t*)(dst + (long)(c0 + c) * R + r0 + r2) = v;
        }
        __syncthreads();
    }
}

// sum 4 split-K partials [d][k], apply per-k renorm inv, transpose -> [k][d],
// decompose hi/lo.
__global__ void reduce_tr(const float* __restrict__ cp, const float* __restrict__ part,
                          __nv_bfloat16* __restrict__ UH, __nv_bfloat16* __restrict__ UL) {
    __shared__ float t[64 * 65];
    __shared__ float inv[64];
    int d0 = blockIdx.x * 64, b = blockIdx.y;
    int tid = threadIdx.x;
    if (tid < 64) {
        float s = 0.f;
#pragma unroll
        for (int j = 0; j < 32; j++) s += part[(b * 32 + j) * 64 + tid];
        inv[tid] = 1.f / (s + EPS_F);
    }
    const float* base = cp + (long)(b * 4) * DD * NS + (long)d0 * NS;
#pragma unroll
    for (int j = 0; j < 4; j++) {
        int u = tid + j * 256;
        int du = u >> 4, kq = (u & 15);
        float4 acc = ((const float4*)(base + (long)du * NS))[kq];
#pragma unroll
        for (int sl = 1; sl < 4; sl++) {
            float4 v = ((const float4*)(base + (long)sl * DD * NS + (long)du * NS))[kq];
            acc.x += v.x; acc.y += v.y; acc.z += v.z; acc.w += v.w;
        }
        t[du * 65 + kq * 4 + 0] = acc.x;
        t[du * 65 + kq * 4 + 1] = acc.y;
        t[du * 65 + kq * 4 + 2] = acc.z;
        t[du * 65 + kq * 4 + 3] = acc.w;
    }
    __syncthreads();
#pragma unroll
    for (int j = 0; j < 8; j++) {
        int u = tid + j * 256;
        int k = u >> 5, d2i = (u & 31) * 2;
        float iv = inv[k];
        float v0 = t[(d2i + 0) * 65 + k] * iv;
        float v1 = t[(d2i + 1) * 65 + k] * iv;
        float h0, l0, h1, l1;
        d2(v0, h0, l0); d2(v1, h1, l1);
        long o = ((long)b * NS + k) * DD + d0 + d2i;
        *(uint32_t*)(UH + o) = pack2(h0, h1);
        *(uint32_t*)(UL + o) = pack2(l0, l1);
    }
}

// GRU pointwise + raw hi/lo + fused rmsnorm/decomp of new slots (1 block/row)
__global__ void gru_combine_norm(const float* __restrict__ gcat,
                                 float* __restrict__ slots,
                                 __nv_bfloat16* __restrict__ SH, __nv_bfloat16* __restrict__ SL,
                                 __nv_bfloat16* __restrict__ SNH, __nv_bfloat16* __restrict__ SNL,
                                 const float* __restrict__ snw) {
    long r = blockIdx.x;
    int t = threadIdx.x;
    long b3 = r * 3 * DD;
    float4 xr = ((const float4*)(gcat + b3))[t];
    float4 xz = ((const float4*)(gcat + b3 + DD))[t];
    float4 xn = ((const float4*)(gcat + b3 + 2 * DD))[t];
    float4 hr = ((const float4*)(gcat + G_OFF + b3))[t];
    float4 hz = ((const float4*)(gcat + G_OFF + b3 + DD))[t];
    float4 hn = ((const float4*)(gcat + G_OFF + b3 + 2 * DD))[t];
    float4 hprev = ((const float4*)(slots + r * DD))[t];
    float4 o;
    {
        float rg = 1.f / (1.f + __expf(-(xr.x + hr.x)));
        float zg = 1.f / (1.f + __expf(-(xz.x + hz.x)));
        o.x = (1.f - zg) * tanhf(xn.x + rg * hn.x) + zg * hprev.x;
        rg = 1.f / (1.f + __expf(-(xr.y + hr.y)));
        zg = 1.f / (1.f + __expf(-(xz.y + hz.y)));
        o.y = (1.f - zg) * tanhf(xn.y + rg * hn.y) + zg * hprev.y;
        rg = 1.f / (1.f + __expf(-(xr.z + hr.z)));
        zg = 1.f / (1.f + __expf(-(xz.z + hz.z)));
        o.z = (1.f - zg) * tanhf(xn.z + rg * hn.z) + zg * hprev.z;
        rg = 1.f / (1.f + __expf(-(xr.w + hr.w)));
        zg = 1.f / (1.f + __expf(-(xz.w + hz.w)));
        o.w = (1.f - zg) * tanhf(xn.w + rg * hn.w) + zg * hprev.w;
    }
    ((float4*)(slots + r * DD))[t] = o;
    float h0, h1, h2, h3, l0, l1, l2, l3;
    d2(o.x, h0, l0); d2(o.y, h1, l1); d2(o.z, h2, l2); d2(o.w, h3, l3);
    ((uint2*)SH)[r * 256 + t] = make_uint2(pack2(h0, h1), pack2(h2, h3));
    ((uint2*)SL)[r * 256 + t] = make_uint2(pack2(l0, l1), pack2(l2, l3));
    float s = o.x * o.x + o.y * o.y + o.z * o.z + o.w * o.w;
    for (int off = 16; off; off >>= 1) s += __shfl_xor_sync(0xffffffffu, s, off);
    __shared__ float red[8];
    __shared__ float srs;
    if ((t & 31) == 0) red[t >> 5] = s;
    __syncthreads();
    if (t == 0) {
        float tt = 0.f;
#pragma unroll
        for (int i = 0; i < 8; i++) tt += red[i];
        srs = rsqrtf(tt * (1.f / DD) + EPS_F);
    }
    __syncthreads();
    float rs = srs;
    float4 ww = ((const float4*)snw)[t];
    d2(o.x * rs * ww.x, h0, l0); d2(o.y * rs * ww.y, h1, l1);
    d2(o.z * rs * ww.z, h2, l2); d2(o.w * rs * ww.w, h3, l3);
    ((uint2*)SNH)[r * 256 + t] = make_uint2(pack2(h0, h1), pack2(h2, h3));
    ((uint2*)SNL)[r * 256 + t] = make_uint2(pack2(l0, l1), pack2(l2, l3));
}

// ---------------------------------------------------------------------------
// Launch
// ---------------------------------------------------------------------------
extern "C" void kernel_launch(void* const* d_in, const int* in_sizes, int n_in,
                              void* d_out, int out_size)
{
    const float* slots_in = (const float*)d_in[0];
    const float* P        = (const float*)d_in[1];
    const float* Wq       = (const float*)d_in[2];
    const float* Wk       = (const float*)d_in[3];
    const float* Wv       = (const float*)d_in[4];
    const float* wih      = (const float*)d_in[5];
    const float* whh      = (const float*)d_in[6];
    const float* bih      = (const float*)d_in[7];
    const float* bhh      = (const float*)d_in[8];
    const float* snw      = (const float*)d_in[9];
    const float* inw      = (const float*)d_in[10];

    __nv_bfloat16 *pnh, *pnl, *pth, *ptl;
    __nv_bfloat16 *wqh, *wql, *wkh, *wkl, *wvh, *wvl;
    __nv_bfloat16 *wqth, *wqtl, *wkth, *wktl, *wqkth, *wqktl, *wbh, *wbl;
    __nv_bfloat16 *ush, *usl, *awh, *awl, *snh, *snl, *qkh, *qkl, *ath, *atl;
    float *slots, *gcat, *bias2, *partp, *cpart;
    cudaGetSymbolAddress((void**)&pnh, g_pnh);     cudaGetSymbolAddress((void**)&pnl, g_pnl);
    cudaGetSymbolAddress((void**)&pth, g_pth);     cudaGetSymbolAddress((void**)&ptl, g_ptl);
    cudaGetSymbolAddress((void**)&wqh, g_wqh);     cudaGetSymbolAddress((void**)&wql, g_wql);
    cudaGetSymbolAddress((void**)&wkh, g_wkh);     cudaGetSymbolAddress((void**)&wkl, g_wkl);
    cudaGetSymbolAddress((void**)&wvh, g_wvh);     cudaGetSymbolAddress((void**)&wvl, g_wvl);
    cudaGetSymbolAddress((void**)&wqth, g_wqth);   cudaGetSymbolAddress((void**)&wqtl, g_wqtl);
    cudaGetSymbolAddress((void**)&wkth, g_wkth);   cudaGetSymbolAddress((void**)&wktl, g_wktl);
    cudaGetSymbolAddress((void**)&wqkth, g_wqkth); cudaGetSymbolAddress((void**)&wqktl, g_wqktl);
    cudaGetSymbolAddress((void**)&wbh, g_wbh);     cudaGetSymbolAddress((void**)&wbl, g_wbl);
    cudaGetSymbolAddress((void**)&ush, g_ush);     cudaGetSymbolAddress((void**)&usl, g_usl);
    cudaGetSymbolAddress((void**)&awh, g_awh);     cudaGetSymbolAddress((void**)&awl, g_awl);
    cudaGetSymbolAddress((void**)&snh, g_snh);     cudaGetSymbolAddress((void**)&snl, g_snl);
    cudaGetSymbolAddress((void**)&qkh, g_qkh);     cudaGetSymbolAddress((void**)&qkl, g_qkl);
    cudaGetSymbolAddress((void**)&ath, g_ath);     cudaGetSymbolAddress((void**)&atl, g_atl);
    cudaGetSymbolAddress((void**)&slots, g_slots);
    cudaGetSymbolAddress((void**)&gcat, g_gcat);
    cudaGetSymbolAddress((void**)&bias2, g_bias2);
    cudaGetSymbolAddress((void**)&partp, g_part);
    cudaGetSymbolAddress((void**)&cpart, g_cpart);

    constexpr int SM_128_64 = (128 + 64) * 160 * 3;  // 92160
    constexpr int SM_64_128 = (64 + 128) * 160 * 3;  // 92160
    constexpr int SM_64_64  = (64 + 64) * 160 * 3;   // 61440
    cudaFuncSetAttribute(mma_nt<128,64,3>, cudaFuncAttributeMaxDynamicSharedMemorySize, SM_128_64);
    cudaFuncSetAttribute(mma_nt<128,64,0>, cudaFuncAttributeMaxDynamicSharedMemorySize, SM_128_64);
    cudaFuncSetAttribute(mma_nt<64,128,0>, cudaFuncAttributeMaxDynamicSharedMemorySize, SM_64_128);
    cudaFuncSetAttribute(mma_nt<64,64,1>,  cudaFuncAttributeMaxDynamicSharedMemorySize, SM_64_64);

    // ---- weight decomposition (single batched launch) ----
    {
        long nW = DD * DD / 4;
        long nG = 3 * DD * DD / 4;
        long tot = 3 * nW + 2 * nG;
        decomp5<<<(int)((tot + 255) / 256), 256>>>(
            Wq, wqh, wql, nW, Wk, wkh, wkl, nW, Wv, wvh, wvl, nW,
            wih, wbh, wbl, nG, whh, wbh + W_OFF, wbl + W_OFF, nG);
    }
    cudaMemcpyAsync(bias2, bih, 3 * DD * sizeof(float), cudaMemcpyDeviceToDevice, 0);
    cudaMemcpyAsync(bias2 + 3 * DD, bhh, 3 * DD * sizeof(float), cudaMemcpyDeviceToDevice, 0);

    // ---- WqkT = (Wq^T Wk)^T (split-K x2, fp32 partials, then reduce) ----
    trans_pair<<<dim3(16, 16), 256>>>(wqh, wql, wqth, wqtl, DD, DD);
    trans_pair<<<dim3(16, 16), 256>>>(wkh, wkl, wkth, wktl, DD, DD);
    mma_nt<64,128,0><<<dim3(DD / 128, DD / 64, 2), 256, SM_64_128>>>(
        wkth, wktl, DD, 0, wqth, wqtl, DD, 0,
        cpart, nullptr, nullptr, DD, (long)DD * DD, DD / 2, nullptr, 0, 1.f,
        2, DD / 2, DD / 2, nullptr);
    sum2_dec<<<DD * DD / 4 / 256, 256>>>(cpart, wqkth, wqktl, DD * DD / 4);

    // ---- slots init ----
    cudaMemcpyAsync(slots, slots_in, (size_t)NB * NS * DD * sizeof(float),
                    cudaMemcpyDeviceToDevice, 0);
    decomp4<<<NB * NS * DD / 4 / 256, 256>>>(slots, ush + U_OFF, usl + U_OFF, NB * NS * DD / 4);
    rmsdecomp<<<NB * NS, 256>>>(slots, snh, snl, snw);

    // ---- Pn + PnT, rms fused, single P read from HBM ----
    rms_scale_tr<<<NB * NM / 64, 256>>>(P, inw, pnh, pnl, pth, ptl, (long)NB * NM);

    for (int it = 0; it < 3; it++) {
        // qk = sn @ Wqk
        mma_nt<64,64,1><<<dim3(DD / 64, NB * NS / 64, 1), 256, SM_64_64>>>(
            snh, snl, DD, 0, wqkth, wqktl, DD, 0,
            nullptr, qkh, qkl, DD, 0, DD, nullptr, 0, 1.f, 1, 0, 0, nullptr);

        // scores+softmax fused: writes bf16 hi/lo p [b][k][m] + partials
        mma_nt<128,64,3><<<dim3(1, NM / 128, NB), 256, SM_128_64>>>(
            pnh, pnl, DD, (long)NM * DD, qkh, qkl, DD, (long)NS * DD,
            nullptr, ath, atl, NS, 0, DD, nullptr, 0, SCALE_F, 1, 0, 0, partp);

        // aw partials: split-K x4, BM=128
        mma_nt<128,64,0><<<dim3(1, DD / 128, NB * 4), 256, SM_128_64>>>(
            pth, ptl, (long)NB * NM, NM, ath, atl, NM, (long)NS * NM,
            cpart, nullptr, nullptr, NS, (long)DD * NS, NM / 4, nullptr, 0, 1.f,
            4, 1024, 1024, nullptr);
        reduce_tr<<<dim3(DD / 64, NB), 256>>>(cpart, partp, awh, awl);

        // u = aw @ Wv^T -> packed slot 0 of ush
        mma_nt<64,64,1><<<dim3(DD / 64, NB * NS / 64, 1), 256, SM_64_64>>>(
            awh, awl, DD, 0, wvh, wvl, DD, 0,
            nullptr, ush, usl, DD, 0, DD, nullptr, 0, 1.f, 1, 0, 0, nullptr);

        // GRU gates (z=2, TN=128)
        mma_nt<64,128,0><<<dim3(3 * DD / 128, NB * NS / 64, 2), 256, SM_64_128>>>(
            ush, usl, DD, U_OFF, wbh, wbl, DD, W_OFF,
            gcat, nullptr, nullptr, 3 * DD, G_OFF, DD, bias2, 3 * DD, 1.f, 1, 0, 0, nullptr);

        gru_combine_norm<<<NB * NS, 256>>>(gcat, slots, ush + U_OFF, usl + U_OFF,
                                           snh, snl, snw);
    }

    cudaMemcpyAsync(d_out, slots, (size_t)NB * NS * DD * sizeof(float),
                    cudaMemcpyDeviceToDevice, 0);
}

// round 15
// speedup vs baseline: 1.0280x; 1.0280x over previous
#include <cuda_runtime.h>
#include <cuda_bf16.h>
#include <math.h>
#include <stdint.h>

#define DD 1024
#define NB 8
#define NS 64
#define NM 4096
#define EPS_F 1e-6f
#define SCALE_F 0.03125f

// ---------------------------------------------------------------------------
// Scratch (static device globals)
// ---------------------------------------------------------------------------
__device__ __nv_bfloat16 g_pnh[(long)NB*NM*DD], g_pnl[(long)NB*NM*DD];   // rmsnormed P [bm][d]
__device__ __nv_bfloat16 g_pth[(long)NB*NM*DD], g_ptl[(long)NB*NM*DD];   // PnT [d][b*4096+m]
__device__ __nv_bfloat16 g_wqh[DD*DD],  g_wql[DD*DD];
__device__ __nv_bfloat16 g_wkh[DD*DD],  g_wkl[DD*DD];
__device__ __nv_bfloat16 g_wvh[DD*DD],  g_wvl[DD*DD];
__device__ __nv_bfloat16 g_wqth[DD*DD], g_wqtl[DD*DD];    // WqT
__device__ __nv_bfloat16 g_wkth[DD*DD], g_wktl[DD*DD];    // WkT
__device__ __nv_bfloat16 g_wqkth[DD*DD], g_wqktl[DD*DD];  // (Wq^T Wk)^T
__device__ __nv_bfloat16 g_wbh[2L*3*DD*DD], g_wbl[2L*3*DD*DD];    // gates B: [0]=wih, [1]=whh
__device__ __nv_bfloat16 g_ush[2L*NB*NS*DD], g_usl[2L*NB*NS*DD];  // gates A: [0]=u, [1]=slots raw
__device__ __nv_bfloat16 g_awh[NB*NS*DD], g_awl[NB*NS*DD];        // aw = attn @ Pn (renormed)
__device__ float g_gcat[2L*NB*NS*3*DD];                           // [0]=gx [1]=gh
__device__ float g_bias2[2*3*DD];
__device__ float g_slots[NB*NS*DD];
__device__ float g_rsP[NB*NM];
__device__ __nv_bfloat16 g_snh[NB*NS*DD], g_snl[NB*NS*DD];        // normed slots hi/lo
__device__ __nv_bfloat16 g_qkh[NB*NS*DD], g_qkl[NB*NS*DD];
__device__ float g_part[NB*32*64];
__device__ float g_cpart[32L*DD*NS];                              // split-K partials (8MB)
__device__ __nv_bfloat16 g_ath[(long)NB*NS*NM], g_atl[(long)NB*NS*NM];  // p (softmaxed) [b][k][m]

#define U_OFF  ((long)NB*NS*DD)
#define W_OFF  (3L*DD*DD)
#define G_OFF  ((long)NB*NS*3*DD)

// ---------------------------------------------------------------------------
// Helpers
// ---------------------------------------------------------------------------
__device__ __forceinline__ uint32_t smem_u32(const void* p) {
    uint32_t a;
    asm("{ .reg .u64 t; cvta.to.shared.u64 t, %1; cvt.u32.u64 %0, t; }" : "=r"(a) : "l"(p));
    return a;
}
__device__ __forceinline__ void cpa16(uint32_t dst, const void* src) {
    asm volatile("cp.async.cg.shared.global [%0], [%1], 16;" :: "r"(dst), "l"(src) : "memory");
}
#define CP_COMMIT() asm volatile("cp.async.commit_group;" ::: "memory")
#define CP_WAIT2()  asm volatile("cp.async.wait_group 2;" ::: "memory")
#define CP_WAIT0()  asm volatile("cp.async.wait_group 0;" ::: "memory")

#define LDSM4(r, addr) \
    asm volatile("ldmatrix.sync.aligned.m8n8.x4.shared.b16 {%0,%1,%2,%3}, [%4];" \
        : "=r"((r)[0]), "=r"((r)[1]), "=r"((r)[2]), "=r"((r)[3]) : "r"(addr))

#define MMA4(d, a, b0, b1) \
    asm volatile("mma.sync.aligned.m16n8k16.row.col.f32.bf16.bf16.f32 " \
        "{%0,%1,%2,%3},{%4,%5,%6,%7},{%8,%9},{%0,%1,%2,%3};" \
        : "+f"((d)[0]), "+f"((d)[1]), "+f"((d)[2]), "+f"((d)[3]) \
        : "r"((a)[0]), "r"((a)[1]), "r"((a)[2]), "r"((a)[3]), "r"(b0), "r"(b1))

__device__ __forceinline__ uint32_t pack2(float a, float b) {
    __nv_bfloat162 t = __floats2bfloat162_rn(a, b);
    return *reinterpret_cast<uint32_t*>(&t);
}
__device__ __forceinline__ void d2(float v, float& hi, float& lo) {
    __nv_bfloat16 h = __float2bfloat16_rn(v);
    hi = __bfloat162float(h);
    lo = v - hi;
}

// ---------------------------------------------------------------------------
// Prefetch one BK=32 chunk of A(BM rows) + B(TN rows), hi & lo, into a stage.
// ---------------------------------------------------------------------------
template <int BM, int TN>
__device__ __forceinline__ void prefetch_tiles(
    uint32_t stage,
    const __nv_bfloat16* __restrict__ Ah, const __nv_bfloat16* __restrict__ Al,
    const __nv_bfloat16* __restrict__ Bh, const __nv_bfloat16* __restrict__ Bl,
    long lda, long ldb, int m0, int n0, int k0, int tid)
{
    constexpr int AL_OFF = BM * 80;
    constexpr int BH_OFF = 2 * BM * 80;
#pragma unroll
    for (int i = 0; i < BM / 64; i++) {
        int idx = tid + i * 256;
        int r = idx >> 2, ch = idx & 3;
        long g = (long)(m0 + r) * lda + k0 + ch * 8;
        uint32_t d = stage + (uint32_t)(r * 80 + ch * 16);
        cpa16(d, Ah + g);
        cpa16(d + AL_OFF, Al + g);
    }
#pragma unroll
    for (int i = 0; i < TN / 64; i++) {
        int idx = tid + i * 256;
        int r = idx >> 2, ch = idx & 3;
        long g = (long)(n0 + r) * ldb + k0 + ch * 8;
        uint32_t d = stage + BH_OFF + (uint32_t)(r * 80 + ch * 16);
        cpa16(d, Bh + g);
        cpa16(d + TN * 80, Bl + g);
    }
}

// ---------------------------------------------------------------------------
// bf16x3 NT GEMM via mma.sync, 3-stage cp.async pipeline, 8 warps, 2 CTAs/SM.
// Split-K: blockIdx.z = zb*nsplit + zk.
// EPI: 0 = fp32 out (alpha, bias)   C[m][n]
//      1 = bf16 hi/lo out           C[m][n]
//      3 = softmax over n (TN=64, BM=128, grid.x==1), then bf16 hi/lo
//          TRANSPOSED store Ct[n][m] (un-renormalized) + column partials
// ---------------------------------------------------------------------------
template <int BM, int TN, int EPI>
__global__ __launch_bounds__(256, 2)
void mma_nt(const __nv_bfloat16* __restrict__ Ah, const __nv_bfloat16* __restrict__ Al,
            long lda, long sA,
            const __nv_bfloat16* __restrict__ Bh, const __nv_bfloat16* __restrict__ Bl,
            long ldb, long sB,
            float* __restrict__ Cf,
            __nv_bfloat16* __restrict__ Ch, __nv_bfloat16* __restrict__ Cl,
            long ldc, long sC,
            int Kd, const float* __restrict__ bias, long sBias, float alpha,
            int nsplit, long sAk, long sBk, float* __restrict__ part)
{
    constexpr int WMW = BM / 32;
    constexpr int WNW = 8 / WMW;
    constexpr int WN = TN / WNW;
    constexpr int NF = WN / 8;
    constexpr int NF16 = WN / 16;
    constexpr int AL_OFF = BM * 80;
    constexpr int BH_OFF = 2 * BM * 80;
    constexpr int STAGE = (BM + TN) * 160;

    extern __shared__ char smem[];
    const uint32_t sb = smem_u32(smem);
    const int tid = threadIdx.x, lane = tid & 31, wid = tid >> 5;
    const int wm = wid % WMW, wn = wid / WMW;

    const int m0 = blockIdx.y * BM, n0 = blockIdx.x * TN;
    int zb = blockIdx.z, zk = 0;
    if (nsplit > 1) { zb = blockIdx.z / nsplit; zk = blockIdx.z % nsplit; }
    Ah += (long)zb * sA + (long)zk * sAk;  Al += (long)zb * sA + (long)zk * sAk;
    Bh += (long)zb * sB + (long)zk * sBk;  Bl += (long)zb * sB + (long)zk * sBk;
    if (bias) bias += (long)zb * sBias;

    float acc[2][NF][4];
#pragma unroll
    for (int i = 0; i < 2; i++)
#pragma unroll
        for (int j = 0; j < NF; j++)
#pragma unroll
            for (int k = 0; k < 4; k++) acc[i][j][k] = 0.f;

    const uint32_t aoff = (uint32_t)((wm * 32 + (lane & 15)) * 80 + (lane >> 4) * 16);
    const uint32_t boff = (uint32_t)(BH_OFF + (wn * WN + (lane & 15)) * 80 + (lane >> 4) * 16);

    const int NC = Kd >> 5;
    prefetch_tiles<BM, TN>(sb,             Ah, Al, Bh, Bl, lda, ldb, m0, n0, 0,  tid);
    CP_COMMIT();
    prefetch_tiles<BM, TN>(sb + STAGE,     Ah, Al, Bh, Bl, lda, ldb, m0, n0, 32, tid);
    CP_COMMIT();
    prefetch_tiles<BM, TN>(sb + 2 * STAGE, Ah, Al, Bh, Bl, lda, ldb, m0, n0, 64, tid);
    CP_COMMIT();

    int sidx = 0;
    for (int c = 0; c < NC; c++) {
        CP_WAIT2();
        __syncthreads();
        const uint32_t st = sb + sidx * STAGE;
#pragma unroll
        for (int ks = 0; ks < 2; ks++) {
            const uint32_t ka = st + aoff + ks * 32;
            const uint32_t kb = st + boff + ks * 32;
            uint32_t ah[2][4], al[2][4];
            LDSM4(ah[0], ka);
            LDSM4(ah[1], ka + 16 * 80);
            LDSM4(al[0], ka + AL_OFF);
            LDSM4(al[1], ka + AL_OFF + 16 * 80);
            uint32_t bh[NF16][4], bl[NF16][4];
#pragma unroll
            for (int nf = 0; nf < NF16; nf++) {
                LDSM4(bh[nf], kb + nf * 16 * 80);
                LDSM4(bl[nf], kb + TN * 80 + nf * 16 * 80);
            }
#pragma unroll
            for (int mf = 0; mf < 2; mf++)
#pragma unroll
                for (int nf = 0; nf < NF16; nf++) {
                    MMA4(acc[mf][2*nf],   ah[mf], bh[nf][0], bh[nf][2]);
                    MMA4(acc[mf][2*nf+1], ah[mf], bh[nf][1], bh[nf][3]);
                    MMA4(acc[mf][2*nf],   ah[mf], bl[nf][0], bl[nf][2]);
                    MMA4(acc[mf][2*nf+1], ah[mf], bl[nf][1], bl[nf][3]);
                    MMA4(acc[mf][2*nf],   al[mf], bh[nf][0], bh[nf][2]);
                    MMA4(acc[mf][2*nf+1], al[mf], bh[nf][1], bh[nf][3]);
                }
        }
        __syncthreads();
        if (c + 3 < NC)
            prefetch_tiles<BM, TN>(sb + sidx * STAGE, Ah, Al, Bh, Bl,
                                   lda, ldb, m0, n0, (c + 3) * 32, tid);
        CP_COMMIT();
        sidx = (sidx == 2) ? 0 : sidx + 1;
    }
    CP_WAIT0();
    __syncthreads();

    // ---- epilogue ----
    const int rbase = m0 + wm * 32;
    const int cbase = n0 + wn * WN;
    if (EPI == 0) {
        float* C = Cf + (long)blockIdx.z * sC;
#pragma unroll
        for (int mf = 0; mf < 2; mf++) {
            int row = rbase + mf * 16 + (lane >> 2);
#pragma unroll
            for (int nf = 0; nf < NF; nf++) {
                int col = cbase + nf * 8 + (lane & 3) * 2;
                float b0 = bias ? bias[col] : 0.f, b1 = bias ? bias[col + 1] : 0.f;
                float2 v0 = make_float2(acc[mf][nf][0] * alpha + b0,
                                        acc[mf][nf][1] * alpha + b1);
                float2 v1 = make_float2(acc[mf][nf][2] * alpha + b0,
                                        acc[mf][nf][3] * alpha + b1);
                *(float2*)(C + (long)row * ldc + col) = v0;
                *(float2*)(C + (long)(row + 8) * ldc + col) = v1;
            }
        }
    } else if (EPI == 1) {
        __nv_bfloat16* CH = Ch + (long)blockIdx.z * sC;
        __nv_bfloat16* CL = Cl + (long)blockIdx.z * sC;
#pragma unroll
        for (int mf = 0; mf < 2; mf++) {
            int row = rbase + mf * 16 + (lane >> 2);
#pragma unroll
            for (int nf = 0; nf < NF; nf++) {
                int col = cbase + nf * 8 + (lane & 3) * 2;
                float h0, l0, h1, l1;
                d2(acc[mf][nf][0] * alpha, h0, l0);
                d2(acc[mf][nf][1] * alpha, h1, l1);
                *(uint32_t*)(CH + (long)row * ldc + col) = pack2(h0, h1);
                *(uint32_t*)(CL + (long)row * ldc + col) = pack2(l0, l1);
                d2(acc[mf][nf][2] * alpha, h0, l0);
                d2(acc[mf][nf][3] * alpha, h1, l1);
                *(uint32_t*)(CH + (long)(row + 8) * ldc + col) = pack2(h0, h1);
                *(uint32_t*)(CL + (long)(row + 8) * ldc + col) = pack2(l0, l1);
            }
        }
    } else {
        // EPI==3: in-CTA softmax over full n (TN==NS), bf16 hi/lo transposed
        // store (un-renormalized) + per-block column partial sums.
        float* ts = reinterpret_cast<float*>(smem);
        const int rl = wm * 32;
        const int cl = wn * WN;
#pragma unroll
        for (int mf = 0; mf < 2; mf++) {
            int row = rl + mf * 16 + (lane >> 2);
#pragma unroll
            for (int nf = 0; nf < NF; nf++) {
                int col = cl + nf * 8 + (lane & 3) * 2;
                ts[(row)     * 65 + col]     = acc[mf][nf][0] * alpha;
                ts[(row)     * 65 + col + 1] = acc[mf][nf][1] * alpha;
                ts[(row + 8) * 65 + col]     = acc[mf][nf][2] * alpha;
                ts[(row + 8) * 65 + col + 1] = acc[mf][nf][3] * alpha;
            }
        }
        __syncthreads();
        {
            int row = tid >> 1, half = tid & 1;
            float* p = ts + row * 65 + half * 32;
            float mx = -INFINITY;
#pragma unroll
            for (int i = 0; i < 32; i++) mx = fmaxf(mx, p[i]);
            mx = fmaxf(mx, __shfl_xor_sync(0xffffffffu, mx, 1));
            float sum = 0.f;
            float e[32];
#pragma unroll
            for (int i = 0; i < 32; i++) { e[i] = __expf(p[i] - mx); sum += e[i]; }
            sum += __shfl_xor_sync(0xffffffffu, sum, 1);
            float inv = 1.f / sum;
#pragma unroll
            for (int i = 0; i < 32; i++) p[i] = e[i] * inv;
        }
        __syncthreads();
        if (tid < 64) {
            float s = 0.f;
#pragma unroll 8
            for (int r = 0; r < 128; r++) s += ts[r * 65 + tid];
            part[((long)blockIdx.z * gridDim.y + blockIdx.y) * 64 + tid] = s;
        }
#pragma unroll
        for (int j = 0; j < 16; j++) {
            int u = tid + j * 256;
            int k = u >> 6, m2 = (u & 63) * 2;
            float v0 = ts[(m2 + 0) * 65 + k];
            float v1 = ts[(m2 + 1) * 65 + k];
            float h0, l0, h1, l1;
            d2(v0, h0, l0); d2(v1, h1, l1);
            long o = ((long)blockIdx.z * 64 + k) * NM + m0 + m2;
            *(uint32_t*)(Ch + o) = pack2(h0, h1);
            *(uint32_t*)(Cl + o) = pack2(l0, l1);
        }
    }
}

// ---------------------------------------------------------------------------
// Elementwise / layout kernels
// ---------------------------------------------------------------------------
__global__ void rms_only(const float* __restrict__ X, float* __restrict__ rs) {
    long r = blockIdx.x;
    float4 v = ((const float4*)(X + r * DD))[threadIdx.x];
    float s = v.x * v.x + v.y * v.y + v.z * v.z + v.w * v.w;
    for (int o = 16; o; o >>= 1) s += __shfl_xor_sync(0xffffffffu, s, o);
    __shared__ float red[8];
    if ((threadIdx.x & 31) == 0) red[threadIdx.x >> 5] = s;
    __syncthreads();
    if (threadIdx.x == 0) {
        float t = 0.f;
#pragma unroll
        for (int i = 0; i < 8; i++) t += red[i];
        rs[r] = rsqrtf(t * (1.f / DD) + EPS_F);
    }
}

// fused scale + decomp + dual-layout write (Pn and PnT) per 64m x 64d tile
__global__ void scale_tr(const float* __restrict__ P, const float* __restrict__ rs,
                         const float* __restrict__ w,
                         __nv_bfloat16* __restrict__ H, __nv_bfloat16* __restrict__ L,
                         __nv_bfloat16* __restrict__ HT, __nv_bfloat16* __restrict__ LT,
                         long R) {
    __shared__ uint16_t th[64][66], tl[64][66];
    int d0 = blockIdx.x * 64;
    long m0 = (long)blockIdx.y * 64;
    int tid = threadIdx.x;
#pragma unroll
    for (int j = 0; j < 4; j++) {
        int u = tid + j * 256;
        int row = u >> 4, c4 = (u & 15) * 4;
        long gi = (m0 + row) * DD + d0 + c4;
        float4 v = *(const float4*)(P + gi);
        float rsv = rs[m0 + row];
        float h0, h1, h2, h3, l0, l1, l2, l3;
        d2(v.x * rsv * w[d0 + c4 + 0], h0, l0);
        d2(v.y * rsv * w[d0 + c4 + 1], h1, l1);
        d2(v.z * rsv * w[d0 + c4 + 2], h2, l2);
        d2(v.w * rsv * w[d0 + c4 + 3], h3, l3);
        *(uint2*)(H + gi) = make_uint2(pack2(h0, h1), pack2(h2, h3));
        *(uint2*)(L + gi) = make_uint2(pack2(l0, l1), pack2(l2, l3));
        uint16_t* hp = (uint16_t*)&th[row][c4];
        uint16_t* lp = (uint16_t*)&tl[row][c4];
        __nv_bfloat16 b;
        b = __float2bfloat16_rn(h0); hp[0] = *(uint16_t*)&b;
        b = __float2bfloat16_rn(h1); hp[1] = *(uint16_t*)&b;
        b = __float2bfloat16_rn(h2); hp[2] = *(uint16_t*)&b;
        b = __float2bfloat16_rn(h3); hp[3] = *(uint16_t*)&b;
        b = __float2bfloat16_rn(l0); lp[0] = *(uint16_t*)&b;
        b = __float2bfloat16_rn(l1); lp[1] = *(uint16_t*)&b;
        b = __float2bfloat16_rn(l2); lp[2] = *(uint16_t*)&b;
        b = __float2bfloat16_rn(l3); lp[3] = *(uint16_t*)&b;
    }
    __syncthreads();
#pragma unroll
    for (int j = 0; j < 8; j++) {
        int u = tid + j * 256;
        int d = u >> 5, m2 = (u & 31) * 2;
        uint32_t vh = (uint32_t)th[m2][d] | ((uint32_t)th[m2 + 1][d] << 16);
        uint32_t vl = (uint32_t)tl[m2][d] | ((uint32_t)tl[m2 + 1][d] << 16);
        long o = (long)(d0 + d) * R + m0 + m2;
        *(uint32_t*)(HT + o) = vh;
        *(uint32_t*)(LT + o) = vl;
    }
}

// slots init: copy fp32, raw hi/lo, fused rmsnorm + normed hi/lo (1 block/row)
__global__ void slots_init(const float* __restrict__ Sin, float* __restrict__ S,
                           __nv_bfloat16* __restrict__ SH, __nv_bfloat16* __restrict__ SL,
                           __nv_bfloat16* __restrict__ SNH, __nv_bfloat16* __restrict__ SNL,
                           const float* __restrict__ snw) {
    long r = blockIdx.x;
    int t = threadIdx.x;
    float4 v = ((const float4*)(Sin + r * DD))[t];
    ((float4*)(S + r * DD))[t] = v;
    float h0, h1, h2, h3, l0, l1, l2, l3;
    d2(v.x, h0, l0); d2(v.y, h1, l1); d2(v.z, h2, l2); d2(v.w, h3, l3);
    ((uint2*)SH)[r * 256 + t] = make_uint2(pack2(h0, h1), pack2(h2, h3));
    ((uint2*)SL)[r * 256 + t] = make_uint2(pack2(l0, l1), pack2(l2, l3));
    float s = v.x * v.x + v.y * v.y + v.z * v.z + v.w * v.w;
    for (int o = 16; o; o >>= 1) s += __shfl_xor_sync(0xffffffffu, s, o);
    __shared__ float red[8];
    __shared__ float srs;
    if ((t & 31) == 0) red[t >> 5] = s;
    __syncthreads();
    if (t == 0) {
        float tt = 0.f;
#pragma unroll
        for (int i = 0; i < 8; i++) tt += red[i];
        srs = rsqrtf(tt * (1.f / DD) + EPS_F);
    }
    __syncthreads();
    float rs = srs;
    float4 ww = ((const float4*)snw)[t];
    d2(v.x * rs * ww.x, h0, l0); d2(v.y * rs * ww.y, h1, l1);
    d2(v.z * rs * ww.z, h2, l2); d2(v.w * rs * ww.w, h3, l3);
    ((uint2*)SNH)[r * 256 + t] = make_uint2(pack2(h0, h1), pack2(h2, h3));
    ((uint2*)SNL)[r * 256 + t] = make_uint2(pack2(l0, l1), pack2(l2, l3));
}

// batched hi/lo decomposition over 5 weight tensors (one launch)
__global__ void decomp5(const float* __restrict__ s0, __nv_bfloat16* d0h, __nv_bfloat16* d0l, long n0,
                        const float* __restrict__ s1, __nv_bfloat16* d1h, __nv_bfloat16* d1l, long n1,
                        const float* __restrict__ s2, __nv_bfloat16* d2h_, __nv_bfloat16* d2l, long n2,
                        const float* __restrict__ s3, __nv_bfloat16* d3h, __nv_bfloat16* d3l, long n3,
                        const float* __restrict__ s4, __nv_bfloat16* d4h, __nv_bfloat16* d4l, long n4c) {
    long i = (long)blockIdx.x * blockDim.x + threadIdx.x;
    const float* src; __nv_bfloat16 *dh, *dl;
    if (i < n0)      { src = s0; dh = d0h; dl = d0l; }
    else if ((i -= n0) < n1) { src = s1; dh = d1h; dl = d1l; }
    else if ((i -= n1) < n2) { src = s2; dh = d2h_; dl = d2l; }
    else if ((i -= n2) < n3) { src = s3; dh = d3h; dl = d3l; }
    else if ((i -= n3) < n4c) { src = s4; dh = d4h; dl = d4l; }
    else return;
    float4 v = ((const float4*)src)[i];
    float h0, h1, h2, h3, l0, l1, l2, l3;
    d2(v.x, h0, l0); d2(v.y, h1, l1); d2(v.z, h2, l2); d2(v.w, h3, l3);
    ((uint2*)dh)[i] = make_uint2(pack2(h0, h1), pack2(h2, h3));
    ((uint2*)dl)[i] = make_uint2(pack2(l0, l1), pack2(l2, l3));
}

// 64x64-tile transpose of a bf16 hi/lo pair: [R][C] -> [C][R]
__global__ void trans_pair(const __nv_bfloat16* __restrict__ H, const __nv_bfloat16* __restrict__ L,
                           __nv_bfloat16* __restrict__ HT, __nv_bfloat16* __restrict__ LT,
                           int C, long R) {
    __shared__ uint16_t t[64][66];
    long r0 = (long)blockIdx.y * 64;
    int c0 = blockIdx.x * 64;
    int tid = threadIdx.x;
#pragma unroll
    for (int pass = 0; pass < 2; pass++) {
        const __nv_bfloat16* src = pass ? L : H;
        __nv_bfloat16* dst = pass ? LT : HT;
#pragma unroll
        for (int j = 0; j < 8; j++) {
            int u = tid + j * 256;
            int r = u >> 5, c2 = (u & 31) * 2;
            uint32_t v = *(const uint32_t*)(src + (r0 + r) * C + c0 + c2);
            t[r][c2] = (uint16_t)(v & 0xffff);
            t[r][c2 + 1] = (uint16_t)(v >> 16);
        }
        __syncthreads();
#pragma unroll
        for (int j = 0; j < 8; j++) {
            int u = tid + j * 256;
            int c = u >> 5, r2 = (u & 31) * 2;
            uint32_t v = (uint32_t)t[r2][c] | ((uint32_t)t[r2 + 1][c] << 16);
            *(uint32_t*)(dst + (long)(c0 + c) * R + r0 + r2) = v;
        }
        __syncthreads();
    }
}

// sum 4 split-K partials [d][k], apply per-k renorm inv, transpose -> [k][d],
// decompose hi/lo.
__global__ void reduce_tr(const float* __restrict__ cp, const float* __restrict__ part,
                          __nv_bfloat16* __restrict__ UH, __nv_bfloat16* __restrict__ UL) {
    __shared__ float t[64 * 65];
    __shared__ float inv[64];
    int d0 = blockIdx.x * 64, b = blockIdx.y;
    int tid = threadIdx.x;
    if (tid < 64) {
        float s = 0.f;
#pragma unroll
        for (int j = 0; j < 32; j++) s += part[(b * 32 + j) * 64 + tid];
        inv[tid] = 1.f / (s + EPS_F);
    }
    const float* base = cp + (long)(b * 4) * DD * NS + (long)d0 * NS;
#pragma unroll
    for (int j = 0; j < 4; j++) {
        int u = tid + j * 256;
        int du = u >> 4, kq = (u & 15);
        float4 acc = ((const float4*)(base + (long)du * NS))[kq];
#pragma unroll
        for (int sl = 1; sl < 4; sl++) {
            float4 v = ((const float4*)(base + (long)sl * DD * NS + (long)du * NS))[kq];
            acc.x += v.x; acc.y += v.y; acc.z += v.z; acc.w += v.w;
        }
        t[du * 65 + kq * 4 + 0] = acc.x;
        t[du * 65 + kq * 4 + 1] = acc.y;
        t[du * 65 + kq * 4 + 2] = acc.z;
        t[du * 65 + kq * 4 + 3] = acc.w;
    }
    __syncthreads();
#pragma unroll
    for (int j = 0; j < 8; j++) {
        int u = tid + j * 256;
        int k = u >> 5, d2i = (u & 31) * 2;
        float iv = inv[k];
        float v0 = t[(d2i + 0) * 65 + k] * iv;
        float v1 = t[(d2i + 1) * 65 + k] * iv;
        float h0, l0, h1, l1;
        d2(v0, h0, l0); d2(v1, h1, l1);
        long o = ((long)b * NS + k) * DD + d0 + d2i;
        *(uint32_t*)(UH + o) = pack2(h0, h1);
        *(uint32_t*)(UL + o) = pack2(l0, l1);
    }
}

// GRU pointwise + raw hi/lo + fused rmsnorm/decomp of new slots (1 block/row)
__global__ void gru_combine_norm(const float* __restrict__ gcat,
                                 float* __restrict__ slots,
                                 __nv_bfloat16* __restrict__ SH, __nv_bfloat16* __restrict__ SL,
                                 __nv_bfloat16* __restrict__ SNH, __nv_bfloat16* __restrict__ SNL,
                                 const float* __restrict__ snw) {
    long r = blockIdx.x;
    int t = threadIdx.x;
    long b3 = r * 3 * DD;
    float4 xr = ((const float4*)(gcat + b3))[t];
    float4 xz = ((const float4*)(gcat + b3 + DD))[t];
    float4 xn = ((const float4*)(gcat + b3 + 2 * DD))[t];
    float4 hr = ((const float4*)(gcat + G_OFF + b3))[t];
    float4 hz = ((const float4*)(gcat + G_OFF + b3 + DD))[t];
    float4 hn = ((const float4*)(gcat + G_OFF + b3 + 2 * DD))[t];
    float4 hprev = ((const float4*)(slots + r * DD))[t];
    float4 o;
    {
        float rg = 1.f / (1.f + __expf(-(xr.x + hr.x)));
        float zg = 1.f / (1.f + __expf(-(xz.x + hz.x)));
        o.x = (1.f - zg) * tanhf(xn.x + rg * hn.x) + zg * hprev.x;
        rg = 1.f / (1.f + __expf(-(xr.y + hr.y)));
        zg = 1.f / (1.f + __expf(-(xz.y + hz.y)));
        o.y = (1.f - zg) * tanhf(xn.y + rg * hn.y) + zg * hprev.y;
        rg = 1.f / (1.f + __expf(-(xr.z + hr.z)));
        zg = 1.f / (1.f + __expf(-(xz.z + hz.z)));
        o.z = (1.f - zg) * tanhf(xn.z + rg * hn.z) + zg * hprev.z;
        rg = 1.f / (1.f + __expf(-(xr.w + hr.w)));
        zg = 1.f / (1.f + __expf(-(xz.w + hz.w)));
        o.w = (1.f - zg) * tanhf(xn.w + rg * hn.w) + zg * hprev.w;
    }
    ((float4*)(slots + r * DD))[t] = o;
    float h0, h1, h2, h3, l0, l1, l2, l3;
    d2(o.x, h0, l0); d2(o.y, h1, l1); d2(o.z, h2, l2); d2(o.w, h3, l3);
    ((uint2*)SH)[r * 256 + t] = make_uint2(pack2(h0, h1), pack2(h2, h3));
    ((uint2*)SL)[r * 256 + t] = make_uint2(pack2(l0, l1), pack2(l2, l3));
    float s = o.x * o.x + o.y * o.y + o.z * o.z + o.w * o.w;
    for (int off = 16; off; off >>= 1) s += __shfl_xor_sync(0xffffffffu, s, off);
    __shared__ float red[8];
    __shared__ float srs;
    if ((t & 31) == 0) red[t >> 5] = s;
    __syncthreads();
    if (t == 0) {
        float tt = 0.f;
#pragma unroll
        for (int i = 0; i < 8; i++) tt += red[i];
        srs = rsqrtf(tt * (1.f / DD) + EPS_F);
    }
    __syncthreads();
    float rs = srs;
    float4 ww = ((const float4*)snw)[t];
    d2(o.x * rs * ww.x, h0, l0); d2(o.y * rs * ww.y, h1, l1);
    d2(o.z * rs * ww.z, h2, l2); d2(o.w * rs * ww.w, h3, l3);
    ((uint2*)SNH)[r * 256 + t] = make_uint2(pack2(h0, h1), pack2(h2, h3));
    ((uint2*)SNL)[r * 256 + t] = make_uint2(pack2(l0, l1), pack2(l2, l3));
}

// ---------------------------------------------------------------------------
// Launch
// ---------------------------------------------------------------------------
extern "C" void kernel_launch(void* const* d_in, const int* in_sizes, int n_in,
                              void* d_out, int out_size)
{
    const float* slots_in = (const float*)d_in[0];
    const float* P        = (const float*)d_in[1];
    const float* Wq       = (const float*)d_in[2];
    const float* Wk       = (const float*)d_in[3];
    const float* Wv       = (const float*)d_in[4];
    const float* wih      = (const float*)d_in[5];
    const float* whh      = (const float*)d_in[6];
    const float* bih      = (const float*)d_in[7];
    const float* bhh      = (const float*)d_in[8];
    const float* snw      = (const float*)d_in[9];
    const float* inw      = (const float*)d_in[10];

    __nv_bfloat16 *pnh, *pnl, *pth, *ptl;
    __nv_bfloat16 *wqh, *wql, *wkh, *wkl, *wvh, *wvl;
    __nv_bfloat16 *wqth, *wqtl, *wkth, *wktl, *wqkth, *wqktl, *wbh, *wbl;
    __nv_bfloat16 *ush, *usl, *awh, *awl, *snh, *snl, *qkh, *qkl, *ath, *atl;
    float *slots, *gcat, *bias2, *partp, *cpart, *rsP;
    cudaGetSymbolAddress((void**)&pnh, g_pnh);     cudaGetSymbolAddress((void**)&pnl, g_pnl);
    cudaGetSymbolAddress((void**)&pth, g_pth);     cudaGetSymbolAddress((void**)&ptl, g_ptl);
    cudaGetSymbolAddress((void**)&wqh, g_wqh);     cudaGetSymbolAddress((void**)&wql, g_wql);
    cudaGetSymbolAddress((void**)&wkh, g_wkh);     cudaGetSymbolAddress((void**)&wkl, g_wkl);
    cudaGetSymbolAddress((void**)&wvh, g_wvh);     cudaGetSymbolAddress((void**)&wvl, g_wvl);
    cudaGetSymbolAddress((void**)&wqth, g_wqth);   cudaGetSymbolAddress((void**)&wqtl, g_wqtl);
    cudaGetSymbolAddress((void**)&wkth, g_wkth);   cudaGetSymbolAddress((void**)&wktl, g_wktl);
    cudaGetSymbolAddress((void**)&wqkth, g_wqkth); cudaGetSymbolAddress((void**)&wqktl, g_wqktl);
    cudaGetSymbolAddress((void**)&wbh, g_wbh);     cudaGetSymbolAddress((void**)&wbl, g_wbl);
    cudaGetSymbolAddress((void**)&ush, g_ush);     cudaGetSymbolAddress((void**)&usl, g_usl);
    cudaGetSymbolAddress((void**)&awh, g_awh);     cudaGetSymbolAddress((void**)&awl, g_awl);
    cudaGetSymbolAddress((void**)&snh, g_snh);     cudaGetSymbolAddress((void**)&snl, g_snl);
    cudaGetSymbolAddress((void**)&qkh, g_qkh);     cudaGetSymbolAddress((void**)&qkl, g_qkl);
    cudaGetSymbolAddress((void**)&ath, g_ath);     cudaGetSymbolAddress((void**)&atl, g_atl);
    cudaGetSymbolAddress((void**)&slots, g_slots);
    cudaGetSymbolAddress((void**)&gcat, g_gcat);
    cudaGetSymbolAddress((void**)&bias2, g_bias2);
    cudaGetSymbolAddress((void**)&partp, g_part);
    cudaGetSymbolAddress((void**)&cpart, g_cpart);
    cudaGetSymbolAddress((void**)&rsP, g_rsP);

    constexpr int SM_128_64 = (128 + 64) * 160 * 3;  // 92160
    constexpr int SM_64_128 = (64 + 128) * 160 * 3;  // 92160
    constexpr int SM_64_64  = (64 + 64) * 160 * 3;   // 61440
    cudaFuncSetAttribute(mma_nt<128,64,3>, cudaFuncAttributeMaxDynamicSharedMemorySize, SM_128_64);
    cudaFuncSetAttribute(mma_nt<128,64,0>, cudaFuncAttributeMaxDynamicSharedMemorySize, SM_128_64);
    cudaFuncSetAttribute(mma_nt<64,128,0>, cudaFuncAttributeMaxDynamicSharedMemorySize, SM_64_128);
    cudaFuncSetAttribute(mma_nt<64,128,1>, cudaFuncAttributeMaxDynamicSharedMemorySize, SM_64_128);
    cudaFuncSetAttribute(mma_nt<64,64,1>,  cudaFuncAttributeMaxDynamicSharedMemorySize, SM_64_64);

    // ---- weight decomposition (single batched launch) ----
    {
        long nW = DD * DD / 4;
        long nG = 3 * DD * DD / 4;
        long tot = 3 * nW + 2 * nG;
        decomp5<<<(int)((tot + 255) / 256), 256>>>(
            Wq, wqh, wql, nW, Wk, wkh, wkl, nW, Wv, wvh, wvl, nW,
            wih, wbh, wbl, nG, whh, wbh + W_OFF, wbl + W_OFF, nG);
    }
    cudaMemcpyAsync(bias2, bih, 3 * DD * sizeof(float), cudaMemcpyDeviceToDevice, 0);
    cudaMemcpyAsync(bias2 + 3 * DD, bhh, 3 * DD * sizeof(float), cudaMemcpyDeviceToDevice, 0);

    // ---- WqkT = (Wq^T Wk)^T ----
    trans_pair<<<dim3(16, 16), 256>>>(wqh, wql, wqth, wqtl, DD, DD);
    trans_pair<<<dim3(16, 16), 256>>>(wkh, wkl, wkth, wktl, DD, DD);
    mma_nt<64,128,1><<<dim3(DD / 128, DD / 64, 1), 256, SM_64_128>>>(
        wkth, wktl, DD, 0, wqth, wqtl, DD, 0,
        nullptr, wqkth, wqktl, DD, 0, DD, nullptr, 0, 1.f, 1, 0, 0, nullptr);

    // ---- slots init: copy + raw hi/lo + rmsnorm + normed hi/lo (one kernel) ----
    slots_init<<<NB * NS, 256>>>(slots_in, slots, ush + U_OFF, usl + U_OFF,
                                 snh, snl, snw);

    // ---- Pn + PnT (rms pass + fused scale/decomp/transpose pass) ----
    rms_only<<<NB * NM, 256>>>(P, rsP);
    scale_tr<<<dim3(DD / 64, NB * NM / 64), 256>>>(P, rsP, inw, pnh, pnl,
                                                   pth, ptl, (long)NB * NM);

    for (int it = 0; it < 3; it++) {
        // qk = sn @ Wqk
        mma_nt<64,64,1><<<dim3(DD / 64, NB * NS / 64, 1), 256, SM_64_64>>>(
            snh, snl, DD, 0, wqkth, wqktl, DD, 0,
            nullptr, qkh, qkl, DD, 0, DD, nullptr, 0, 1.f, 1, 0, 0, nullptr);

        // scores+softmax fused: writes bf16 hi/lo p [b][k][m] + partials
        mma_nt<128,64,3><<<dim3(1, NM / 128, NB), 256, SM_128_64>>>(
            pnh, pnl, DD, (long)NM * DD, qkh, qkl, DD, (long)NS * DD,
            nullptr, ath, atl, NS, 0, DD, nullptr, 0, SCALE_F, 1, 0, 0, partp);

        // aw partials: split-K x4, BM=128
        mma_nt<128,64,0><<<dim3(1, DD / 128, NB * 4), 256, SM_128_64>>>(
            pth, ptl, (long)NB * NM, NM, ath, atl, NM, (long)NS * NM,
            cpart, nullptr, nullptr, NS, (long)DD * NS, NM / 4, nullptr, 0, 1.f,
            4, 1024, 1024, nullptr);
        reduce_tr<<<dim3(DD / 64, NB), 256>>>(cpart, partp, awh, awl);

        // u = aw @ Wv^T -> packed slot 0 of ush
        mma_nt<64,64,1><<<dim3(DD / 64, NB * NS / 64, 1), 256, SM_64_64>>>(
            awh, awl, DD, 0, wvh, wvl, DD, 0,
            nullptr, ush, usl, DD, 0, DD, nullptr, 0, 1.f, 1, 0, 0, nullptr);

        // GRU gates (z=2, TN=128)
        mma_nt<64,128,0><<<dim3(3 * DD / 128, NB * NS / 64, 2), 256, SM_64_128>>>(
            ush, usl, DD, U_OFF, wbh, wbl, DD, W_OFF,
            gcat, nullptr, nullptr, 3 * DD, G_OFF, DD, bias2, 3 * DD, 1.f, 1, 0, 0, nullptr);

        gru_combine_norm<<<NB * NS, 256>>>(gcat, slots, ush + U_OFF, usl + U_OFF,
                                           snh, snl, snw);
    }

    cudaMemcpyAsync(d_out, slots, (size_t)NB * NS * DD * sizeof(float),
                    cudaMemcpyDeviceToDevice, 0);
}

// round 16
// speedup vs baseline: 1.0333x; 1.0052x over previous
#include <cuda_runtime.h>
#include <cuda_bf16.h>
#include <math.h>
#include <stdint.h>

#define DD 1024
#define NB 8
#define NS 64
#define NM 4096
#define EPS_F 1e-6f
#define SCALE_F 0.03125f

// ---------------------------------------------------------------------------
// Scratch (static device globals)
// ---------------------------------------------------------------------------
__device__ __nv_bfloat16 g_pnh[(long)NB*NM*DD], g_pnl[(long)NB*NM*DD];   // rmsnormed P [bm][d]
__device__ __nv_bfloat16 g_pth[(long)NB*NM*DD], g_ptl[(long)NB*NM*DD];   // PnT [d][b*4096+m]
__device__ __nv_bfloat16 g_wqh[DD*DD],  g_wql[DD*DD];
__device__ __nv_bfloat16 g_wkh[DD*DD],  g_wkl[DD*DD];
__device__ __nv_bfloat16 g_wvh[DD*DD],  g_wvl[DD*DD];
__device__ __nv_bfloat16 g_wqth[DD*DD], g_wqtl[DD*DD];    // WqT
__device__ __nv_bfloat16 g_wkth[DD*DD], g_wktl[DD*DD];    // WkT
__device__ __nv_bfloat16 g_wqkth[DD*DD], g_wqktl[DD*DD];  // (Wq^T Wk)^T
__device__ __nv_bfloat16 g_wbh[2L*3*DD*DD], g_wbl[2L*3*DD*DD];    // gates B: [0]=wih, [1]=whh
__device__ __nv_bfloat16 g_ush[2L*NB*NS*DD], g_usl[2L*NB*NS*DD];  // gates A: [0]=u, [1]=slots raw
__device__ __nv_bfloat16 g_awh[NB*NS*DD], g_awl[NB*NS*DD];        // aw = attn @ Pn (renormed)
__device__ float g_gcat[2L*NB*NS*3*DD];                           // [0]=gx [1]=gh
__device__ float g_bias2[2*3*DD];
__device__ float g_slots[NB*NS*DD];
__device__ float g_rsP[NB*NM];
__device__ __nv_bfloat16 g_snh[NB*NS*DD], g_snl[NB*NS*DD];        // normed slots hi/lo
__device__ __nv_bfloat16 g_qkh[NB*NS*DD], g_qkl[NB*NS*DD];
__device__ float g_part[NB*32*64];
__device__ float g_cpart[32L*DD*NS];                              // split-K partials (8MB)
__device__ __nv_bfloat16 g_ath[(long)NB*NS*NM], g_atl[(long)NB*NS*NM];  // p (softmaxed) [b][k][m]

#define U_OFF  ((long)NB*NS*DD)
#define W_OFF  (3L*DD*DD)
#define G_OFF  ((long)NB*NS*3*DD)

// ---------------------------------------------------------------------------
// Helpers
// ---------------------------------------------------------------------------
__device__ __forceinline__ uint32_t smem_u32(const void* p) {
    uint32_t a;
    asm("{ .reg .u64 t; cvta.to.shared.u64 t, %1; cvt.u32.u64 %0, t; }" : "=r"(a) : "l"(p));
    return a;
}
__device__ __forceinline__ void cpa16(uint32_t dst, const void* src) {
    asm volatile("cp.async.cg.shared.global [%0], [%1], 16;" :: "r"(dst), "l"(src) : "memory");
}
#define CP_COMMIT() asm volatile("cp.async.commit_group;" ::: "memory")
#define CP_WAIT2()  asm volatile("cp.async.wait_group 2;" ::: "memory")
#define CP_WAIT0()  asm volatile("cp.async.wait_group 0;" ::: "memory")

#define LDSM4(r, addr) \
    asm volatile("ldmatrix.sync.aligned.m8n8.x4.shared.b16 {%0,%1,%2,%3}, [%4];" \
        : "=r"((r)[0]), "=r"((r)[1]), "=r"((r)[2]), "=r"((r)[3]) : "r"(addr))

#define MMA4(d, a, b0, b1) \
    asm volatile("mma.sync.aligned.m16n8k16.row.col.f32.bf16.bf16.f32 " \
        "{%0,%1,%2,%3},{%4,%5,%6,%7},{%8,%9},{%0,%1,%2,%3};" \
        : "+f"((d)[0]), "+f"((d)[1]), "+f"((d)[2]), "+f"((d)[3]) \
        : "r"((a)[0]), "r"((a)[1]), "r"((a)[2]), "r"((a)[3]), "r"(b0), "r"(b1))

__device__ __forceinline__ uint32_t pack2(float a, float b) {
    __nv_bfloat162 t = __floats2bfloat162_rn(a, b);
    return *reinterpret_cast<uint32_t*>(&t);
}
__device__ __forceinline__ void d2(float v, float& hi, float& lo) {
    __nv_bfloat16 h = __float2bfloat16_rn(v);
    hi = __bfloat162float(h);
    lo = v - hi;
}

// ---------------------------------------------------------------------------
// Prefetch one BK=32 chunk of A(BM rows) + B(TN rows), hi & lo, into a stage.
// ---------------------------------------------------------------------------
template <int BM, int TN>
__device__ __forceinline__ void prefetch_tiles(
    uint32_t stage,
    const __nv_bfloat16* __restrict__ Ah, const __nv_bfloat16* __restrict__ Al,
    const __nv_bfloat16* __restrict__ Bh, const __nv_bfloat16* __restrict__ Bl,
    long lda, long ldb, int m0, int n0, int k0, int tid)
{
    constexpr int AL_OFF = BM * 80;
    constexpr int BH_OFF = 2 * BM * 80;
#pragma unroll
    for (int i = 0; i < BM / 64; i++) {
        int idx = tid + i * 256;
        int r = idx >> 2, ch = idx & 3;
        long g = (long)(m0 + r) * lda + k0 + ch * 8;
        uint32_t d = stage + (uint32_t)(r * 80 + ch * 16);
        cpa16(d, Ah + g);
        cpa16(d + AL_OFF, Al + g);
    }
#pragma unroll
    for (int i = 0; i < TN / 64; i++) {
        int idx = tid + i * 256;
        int r = idx >> 2, ch = idx & 3;
        long g = (long)(n0 + r) * ldb + k0 + ch * 8;
        uint32_t d = stage + BH_OFF + (uint32_t)(r * 80 + ch * 16);
        cpa16(d, Bh + g);
        cpa16(d + TN * 80, Bl + g);
    }
}

// ---------------------------------------------------------------------------
// bf16x3 NT GEMM via mma.sync, 3-stage cp.async pipeline, 8 warps, 2 CTAs/SM.
// Split-K: blockIdx.z = zb*nsplit + zk.
// EPI: 0 = fp32 out (alpha, bias)   C[m][n]
//      1 = bf16 hi/lo out           C[m][n]
//      3 = softmax over n (TN=64, BM=128, grid.x==1), then bf16 hi/lo
//          TRANSPOSED store Ct[n][m] (un-renormalized) + column partials
// ---------------------------------------------------------------------------
template <int BM, int TN, int EPI>
__global__ __launch_bounds__(256, 2)
void mma_nt(const __nv_bfloat16* __restrict__ Ah, const __nv_bfloat16* __restrict__ Al,
            long lda, long sA,
            const __nv_bfloat16* __restrict__ Bh, const __nv_bfloat16* __restrict__ Bl,
            long ldb, long sB,
            float* __restrict__ Cf,
            __nv_bfloat16* __restrict__ Ch, __nv_bfloat16* __restrict__ Cl,
            long ldc, long sC,
            int Kd, const float* __restrict__ bias, long sBias, float alpha,
            int nsplit, long sAk, long sBk, float* __restrict__ part)
{
    constexpr int WMW = BM / 32;
    constexpr int WNW = 8 / WMW;
    constexpr int WN = TN / WNW;
    constexpr int NF = WN / 8;
    constexpr int NF16 = WN / 16;
    constexpr int AL_OFF = BM * 80;
    constexpr int BH_OFF = 2 * BM * 80;
    constexpr int STAGE = (BM + TN) * 160;

    extern __shared__ char smem[];
    const uint32_t sb = smem_u32(smem);
    const int tid = threadIdx.x, lane = tid & 31, wid = tid >> 5;
    const int wm = wid % WMW, wn = wid / WMW;

    const int m0 = blockIdx.y * BM, n0 = blockIdx.x * TN;
    int zb = blockIdx.z, zk = 0;
    if (nsplit > 1) { zb = blockIdx.z / nsplit; zk = blockIdx.z % nsplit; }
    Ah += (long)zb * sA + (long)zk * sAk;  Al += (long)zb * sA + (long)zk * sAk;
    Bh += (long)zb * sB + (long)zk * sBk;  Bl += (long)zb * sB + (long)zk * sBk;
    if (bias) bias += (long)zb * sBias;

    float acc[2][NF][4];
#pragma unroll
    for (int i = 0; i < 2; i++)
#pragma unroll
        for (int j = 0; j < NF; j++)
#pragma unroll
            for (int k = 0; k < 4; k++) acc[i][j][k] = 0.f;

    const uint32_t aoff = (uint32_t)((wm * 32 + (lane & 15)) * 80 + (lane >> 4) * 16);
    const uint32_t boff = (uint32_t)(BH_OFF + (wn * WN + (lane & 15)) * 80 + (lane >> 4) * 16);

    const int NC = Kd >> 5;
    prefetch_tiles<BM, TN>(sb,             Ah, Al, Bh, Bl, lda, ldb, m0, n0, 0,  tid);
    CP_COMMIT();
    prefetch_tiles<BM, TN>(sb + STAGE,     Ah, Al, Bh, Bl, lda, ldb, m0, n0, 32, tid);
    CP_COMMIT();
    prefetch_tiles<BM, TN>(sb + 2 * STAGE, Ah, Al, Bh, Bl, lda, ldb, m0, n0, 64, tid);
    CP_COMMIT();

    int sidx = 0;
    for (int c = 0; c < NC; c++) {
        CP_WAIT2();
        __syncthreads();
        const uint32_t st = sb + sidx * STAGE;
#pragma unroll
        for (int ks = 0; ks < 2; ks++) {
            const uint32_t ka = st + aoff + ks * 32;
            const uint32_t kb = st + boff + ks * 32;
            uint32_t ah[2][4], al[2][4];
            LDSM4(ah[0], ka);
            LDSM4(ah[1], ka + 16 * 80);
            LDSM4(al[0], ka + AL_OFF);
            LDSM4(al[1], ka + AL_OFF + 16 * 80);
            uint32_t bh[NF16][4], bl[NF16][4];
#pragma unroll
            for (int nf = 0; nf < NF16; nf++) {
                LDSM4(bh[nf], kb + nf * 16 * 80);
                LDSM4(bl[nf], kb + TN * 80 + nf * 16 * 80);
            }
#pragma unroll
            for (int mf = 0; mf < 2; mf++)
#pragma unroll
                for (int nf = 0; nf < NF16; nf++) {
                    MMA4(acc[mf][2*nf],   ah[mf], bh[nf][0], bh[nf][2]);
                    MMA4(acc[mf][2*nf+1], ah[mf], bh[nf][1], bh[nf][3]);
                    MMA4(acc[mf][2*nf],   ah[mf], bl[nf][0], bl[nf][2]);
                    MMA4(acc[mf][2*nf+1], ah[mf], bl[nf][1], bl[nf][3]);
                    MMA4(acc[mf][2*nf],   al[mf], bh[nf][0], bh[nf][2]);
                    MMA4(acc[mf][2*nf+1], al[mf], bh[nf][1], bh[nf][3]);
                }
        }
        __syncthreads();
        if (c + 3 < NC)
            prefetch_tiles<BM, TN>(sb + sidx * STAGE, Ah, Al, Bh, Bl,
                                   lda, ldb, m0, n0, (c + 3) * 32, tid);
        CP_COMMIT();
        sidx = (sidx == 2) ? 0 : sidx + 1;
    }
    CP_WAIT0();
    __syncthreads();

    // ---- epilogue ----
    const int rbase = m0 + wm * 32;
    const int cbase = n0 + wn * WN;
    if (EPI == 0) {
        float* C = Cf + (long)blockIdx.z * sC;
#pragma unroll
        for (int mf = 0; mf < 2; mf++) {
            int row = rbase + mf * 16 + (lane >> 2);
#pragma unroll
            for (int nf = 0; nf < NF; nf++) {
                int col = cbase + nf * 8 + (lane & 3) * 2;
                float b0 = bias ? bias[col] : 0.f, b1 = bias ? bias[col + 1] : 0.f;
                float2 v0 = make_float2(acc[mf][nf][0] * alpha + b0,
                                        acc[mf][nf][1] * alpha + b1);
                float2 v1 = make_float2(acc[mf][nf][2] * alpha + b0,
                                        acc[mf][nf][3] * alpha + b1);
                *(float2*)(C + (long)row * ldc + col) = v0;
                *(float2*)(C + (long)(row + 8) * ldc + col) = v1;
            }
        }
    } else if (EPI == 1) {
        __nv_bfloat16* CH = Ch + (long)blockIdx.z * sC;
        __nv_bfloat16* CL = Cl + (long)blockIdx.z * sC;
#pragma unroll
        for (int mf = 0; mf < 2; mf++) {
            int row = rbase + mf * 16 + (lane >> 2);
#pragma unroll
            for (int nf = 0; nf < NF; nf++) {
                int col = cbase + nf * 8 + (lane & 3) * 2;
                float h0, l0, h1, l1;
                d2(acc[mf][nf][0] * alpha, h0, l0);
                d2(acc[mf][nf][1] * alpha, h1, l1);
                *(uint32_t*)(CH + (long)row * ldc + col) = pack2(h0, h1);
                *(uint32_t*)(CL + (long)row * ldc + col) = pack2(l0, l1);
                d2(acc[mf][nf][2] * alpha, h0, l0);
                d2(acc[mf][nf][3] * alpha, h1, l1);
                *(uint32_t*)(CH + (long)(row + 8) * ldc + col) = pack2(h0, h1);
                *(uint32_t*)(CL + (long)(row + 8) * ldc + col) = pack2(l0, l1);
            }
        }
    } else {
        // EPI==3: in-CTA softmax over full n (TN==NS), bf16 hi/lo transposed
        // store (un-renormalized) + per-block column partial sums.
        float* ts = reinterpret_cast<float*>(smem);
        const int rl = wm * 32;
        const int cl = wn * WN;
#pragma unroll
        for (int mf = 0; mf < 2; mf++) {
            int row = rl + mf * 16 + (lane >> 2);
#pragma unroll
            for (int nf = 0; nf < NF; nf++) {
                int col = cl + nf * 8 + (lane & 3) * 2;
                ts[(row)     * 65 + col]     = acc[mf][nf][0] * alpha;
                ts[(row)     * 65 + col + 1] = acc[mf][nf][1] * alpha;
                ts[(row + 8) * 65 + col]     = acc[mf][nf][2] * alpha;
                ts[(row + 8) * 65 + col + 1] = acc[mf][nf][3] * alpha;
            }
        }
        __syncthreads();
        {
            int row = tid >> 1, half = tid & 1;
            float* p = ts + row * 65 + half * 32;
            float mx = -INFINITY;
#pragma unroll
            for (int i = 0; i < 32; i++) mx = fmaxf(mx, p[i]);
            mx = fmaxf(mx, __shfl_xor_sync(0xffffffffu, mx, 1));
            float sum = 0.f;
            float e[32];
#pragma unroll
            for (int i = 0; i < 32; i++) { e[i] = __expf(p[i] - mx); sum += e[i]; }
            sum += __shfl_xor_sync(0xffffffffu, sum, 1);
            float inv = 1.f / sum;
#pragma unroll
            for (int i = 0; i < 32; i++) p[i] = e[i] * inv;
        }
        __syncthreads();
        if (tid < 64) {
            float s = 0.f;
#pragma unroll 8
            for (int r = 0; r < 128; r++) s += ts[r * 65 + tid];
            part[((long)blockIdx.z * gridDim.y + blockIdx.y) * 64 + tid] = s;
        }
#pragma unroll
        for (int j = 0; j < 16; j++) {
            int u = tid + j * 256;
            int k = u >> 6, m2 = (u & 63) * 2;
            float v0 = ts[(m2 + 0) * 65 + k];
            float v1 = ts[(m2 + 1) * 65 + k];
            float h0, l0, h1, l1;
            d2(v0, h0, l0); d2(v1, h1, l1);
            long o = ((long)blockIdx.z * 64 + k) * NM + m0 + m2;
            *(uint32_t*)(Ch + o) = pack2(h0, h1);
            *(uint32_t*)(Cl + o) = pack2(l0, l1);
        }
    }
}

// ---------------------------------------------------------------------------
// Elementwise / layout kernels
// ---------------------------------------------------------------------------
__global__ void rms_only(const float* __restrict__ X, float* __restrict__ rs) {
    long r = blockIdx.x;
    float4 v = ((const float4*)(X + r * DD))[threadIdx.x];
    float s = v.x * v.x + v.y * v.y + v.z * v.z + v.w * v.w;
    for (int o = 16; o; o >>= 1) s += __shfl_xor_sync(0xffffffffu, s, o);
    __shared__ float red[8];
    if ((threadIdx.x & 31) == 0) red[threadIdx.x >> 5] = s;
    __syncthreads();
    if (threadIdx.x == 0) {
        float t = 0.f;
#pragma unroll
        for (int i = 0; i < 8; i++) t += red[i];
        rs[r] = rsqrtf(t * (1.f / DD) + EPS_F);
    }
}

// fused scale + decomp + dual-layout write (Pn and PnT) per 64m x 64d tile
__global__ void scale_tr(const float* __restrict__ P, const float* __restrict__ rs,
                         const float* __restrict__ w,
                         __nv_bfloat16* __restrict__ H, __nv_bfloat16* __restrict__ L,
                         __nv_bfloat16* __restrict__ HT, __nv_bfloat16* __restrict__ LT,
                         long R) {
    __shared__ uint16_t th[64][66], tl[64][66];
    int d0 = blockIdx.x * 64;
    long m0 = (long)blockIdx.y * 64;
    int tid = threadIdx.x;
#pragma unroll
    for (int j = 0; j < 4; j++) {
        int u = tid + j * 256;
        int row = u >> 4, c4 = (u & 15) * 4;
        long gi = (m0 + row) * DD + d0 + c4;
        float4 v = *(const float4*)(P + gi);
        float rsv = rs[m0 + row];
        float h0, h1, h2, h3, l0, l1, l2, l3;
        d2(v.x * rsv * w[d0 + c4 + 0], h0, l0);
        d2(v.y * rsv * w[d0 + c4 + 1], h1, l1);
        d2(v.z * rsv * w[d0 + c4 + 2], h2, l2);
        d2(v.w * rsv * w[d0 + c4 + 3], h3, l3);
        *(uint2*)(H + gi) = make_uint2(pack2(h0, h1), pack2(h2, h3));
        *(uint2*)(L + gi) = make_uint2(pack2(l0, l1), pack2(l2, l3));
        uint16_t* hp = (uint16_t*)&th[row][c4];
        uint16_t* lp = (uint16_t*)&tl[row][c4];
        __nv_bfloat16 b;
        b = __float2bfloat16_rn(h0); hp[0] = *(uint16_t*)&b;
        b = __float2bfloat16_rn(h1); hp[1] = *(uint16_t*)&b;
        b = __float2bfloat16_rn(h2); hp[2] = *(uint16_t*)&b;
        b = __float2bfloat16_rn(h3); hp[3] = *(uint16_t*)&b;
        b = __float2bfloat16_rn(l0); lp[0] = *(uint16_t*)&b;
        b = __float2bfloat16_rn(l1); lp[1] = *(uint16_t*)&b;
        b = __float2bfloat16_rn(l2); lp[2] = *(uint16_t*)&b;
        b = __float2bfloat16_rn(l3); lp[3] = *(uint16_t*)&b;
    }
    __syncthreads();
#pragma unroll
    for (int j = 0; j < 8; j++) {
        int u = tid + j * 256;
        int d = u >> 5, m2 = (u & 31) * 2;
        uint32_t vh = (uint32_t)th[m2][d] | ((uint32_t)th[m2 + 1][d] << 16);
        uint32_t vl = (uint32_t)tl[m2][d] | ((uint32_t)tl[m2 + 1][d] << 16);
        long o = (long)(d0 + d) * R + m0 + m2;
        *(uint32_t*)(HT + o) = vh;
        *(uint32_t*)(LT + o) = vl;
    }
}

// slots init: copy fp32, raw hi/lo, fused rmsnorm + normed hi/lo (1 block/row)
__global__ void slots_init(const float* __restrict__ Sin, float* __restrict__ S,
                           __nv_bfloat16* __restrict__ SH, __nv_bfloat16* __restrict__ SL,
                           __nv_bfloat16* __restrict__ SNH, __nv_bfloat16* __restrict__ SNL,
                           const float* __restrict__ snw) {
    long r = blockIdx.x;
    int t = threadIdx.x;
    float4 v = ((const float4*)(Sin + r * DD))[t];
    ((float4*)(S + r * DD))[t] = v;
    float h0, h1, h2, h3, l0, l1, l2, l3;
    d2(v.x, h0, l0); d2(v.y, h1, l1); d2(v.z, h2, l2); d2(v.w, h3, l3);
    ((uint2*)SH)[r * 256 + t] = make_uint2(pack2(h0, h1), pack2(h2, h3));
    ((uint2*)SL)[r * 256 + t] = make_uint2(pack2(l0, l1), pack2(l2, l3));
    float s = v.x * v.x + v.y * v.y + v.z * v.z + v.w * v.w;
    for (int o = 16; o; o >>= 1) s += __shfl_xor_sync(0xffffffffu, s, o);
    __shared__ float red[8];
    __shared__ float srs;
    if ((t & 31) == 0) red[t >> 5] = s;
    __syncthreads();
    if (t == 0) {
        float tt = 0.f;
#pragma unroll
        for (int i = 0; i < 8; i++) tt += red[i];
        srs = rsqrtf(tt * (1.f / DD) + EPS_F);
    }
    __syncthreads();
    float rs = srs;
    float4 ww = ((const float4*)snw)[t];
    d2(v.x * rs * ww.x, h0, l0); d2(v.y * rs * ww.y, h1, l1);
    d2(v.z * rs * ww.z, h2, l2); d2(v.w * rs * ww.w, h3, l3);
    ((uint2*)SNH)[r * 256 + t] = make_uint2(pack2(h0, h1), pack2(h2, h3));
    ((uint2*)SNL)[r * 256 + t] = make_uint2(pack2(l0, l1), pack2(l2, l3));
}

// batched hi/lo decomposition over 5 weight tensors (one launch)
__global__ void decomp5(const float* __restrict__ s0, __nv_bfloat16* d0h, __nv_bfloat16* d0l, long n0,
                        const float* __restrict__ s1, __nv_bfloat16* d1h, __nv_bfloat16* d1l, long n1,
                        const float* __restrict__ s2, __nv_bfloat16* d2h_, __nv_bfloat16* d2l, long n2,
                        const float* __restrict__ s3, __nv_bfloat16* d3h, __nv_bfloat16* d3l, long n3,
                        const float* __restrict__ s4, __nv_bfloat16* d4h, __nv_bfloat16* d4l, long n4c) {
    long i = (long)blockIdx.x * blockDim.x + threadIdx.x;
    const float* src; __nv_bfloat16 *dh, *dl;
    if (i < n0)      { src = s0; dh = d0h; dl = d0l; }
    else if ((i -= n0) < n1) { src = s1; dh = d1h; dl = d1l; }
    else if ((i -= n1) < n2) { src = s2; dh = d2h_; dl = d2l; }
    else if ((i -= n2) < n3) { src = s3; dh = d3h; dl = d3l; }
    else if ((i -= n3) < n4c) { src = s4; dh = d4h; dl = d4l; }
    else return;
    float4 v = ((const float4*)src)[i];
    float h0, h1, h2, h3, l0, l1, l2, l3;
    d2(v.x, h0, l0); d2(v.y, h1, l1); d2(v.z, h2, l2); d2(v.w, h3, l3);
    ((uint2*)dh)[i] = make_uint2(pack2(h0, h1), pack2(h2, h3));
    ((uint2*)dl)[i] = make_uint2(pack2(l0, l1), pack2(l2, l3));
}

// 64x64-tile transpose of TWO bf16 hi/lo pairs (z selects pair): [R][C]->[C][R]
__global__ void trans_pair2(const __nv_bfloat16* __restrict__ H0, const __nv_bfloat16* __restrict__ L0,
                            __nv_bfloat16* __restrict__ HT0, __nv_bfloat16* __restrict__ LT0,
                            const __nv_bfloat16* __restrict__ H1, const __nv_bfloat16* __restrict__ L1,
                            __nv_bfloat16* __restrict__ HT1, __nv_bfloat16* __restrict__ LT1,
                            int C, long R) {
    __shared__ uint16_t t[64][66];
    const __nv_bfloat16* H = blockIdx.z ? H1 : H0;
    const __nv_bfloat16* L = blockIdx.z ? L1 : L0;
    __nv_bfloat16* HT = blockIdx.z ? HT1 : HT0;
    __nv_bfloat16* LT = blockIdx.z ? LT1 : LT0;
    long r0 = (long)blockIdx.y * 64;
    int c0 = blockIdx.x * 64;
    int tid = threadIdx.x;
#pragma unroll
    for (int pass = 0; pass < 2; pass++) {
        const __nv_bfloat16* src = pass ? L : H;
        __nv_bfloat16* dst = pass ? LT : HT;
#pragma unroll
        for (int j = 0; j < 8; j++) {
            int u = tid + j * 256;
            int r = u >> 5, c2 = (u & 31) * 2;
            uint32_t v = *(const uint32_t*)(src + (r0 + r) * C + c0 + c2);
            t[r][c2] = (uint16_t)(v & 0xffff);
            t[r][c2 + 1] = (uint16_t)(v >> 16);
        }
        __syncthreads();
#pragma unroll
        for (int j = 0; j < 8; j++) {
            int u = tid + j * 256;
            int c = u >> 5, r2 = (u & 31) * 2;
            uint32_t v = (uint32_t)t[r2][c] | ((uint32_t)t[r2 + 1][c] << 16);
            *(uint32_t*)(dst + (long)(c0 + c) * R + r0 + r2) = v;
        }
        __syncthreads();
    }
}

// sum 4 split-K partials [d][k], apply per-k renorm inv, transpose -> [k][d],
// decompose hi/lo.
__global__ void reduce_tr(const float* __restrict__ cp, const float* __restrict__ part,
                          __nv_bfloat16* __restrict__ UH, __nv_bfloat16* __restrict__ UL) {
    __shared__ float t[64 * 65];
    __shared__ float inv[64];
    int d0 = blockIdx.x * 64, b = blockIdx.y;
    int tid = threadIdx.x;
    if (tid < 64) {
        float s = 0.f;
#pragma unroll
        for (int j = 0; j < 32; j++) s += part[(b * 32 + j) * 64 + tid];
        inv[tid] = 1.f / (s + EPS_F);
    }
    const float* base = cp + (long)(b * 4) * DD * NS + (long)d0 * NS;
#pragma unroll
    for (int j = 0; j < 4; j++) {
        int u = tid + j * 256;
        int du = u >> 4, kq = (u & 15);
        float4 acc = ((const float4*)(base + (long)du * NS))[kq];
#pragma unroll
        for (int sl = 1; sl < 4; sl++) {
            float4 v = ((const float4*)(base + (long)sl * DD * NS + (long)du * NS))[kq];
            acc.x += v.x; acc.y += v.y; acc.z += v.z; acc.w += v.w;
        }
        t[du * 65 + kq * 4 + 0] = acc.x;
        t[du * 65 + kq * 4 + 1] = acc.y;
        t[du * 65 + kq * 4 + 2] = acc.z;
        t[du * 65 + kq * 4 + 3] = acc.w;
    }
    __syncthreads();
#pragma unroll
    for (int j = 0; j < 8; j++) {
        int u = tid + j * 256;
        int k = u >> 5, d2i = (u & 31) * 2;
        float iv = inv[k];
        float v0 = t[(d2i + 0) * 65 + k] * iv;
        float v1 = t[(d2i + 1) * 65 + k] * iv;
        float h0, l0, h1, l1;
        d2(v0, h0, l0); d2(v1, h1, l1);
        long o = ((long)b * NS + k) * DD + d0 + d2i;
        *(uint32_t*)(UH + o) = pack2(h0, h1);
        *(uint32_t*)(UL + o) = pack2(l0, l1);
    }
}

// GRU pointwise + raw hi/lo + fused rmsnorm/decomp of new slots (1 block/row).
// On the final iteration `out` is non-null: result is also written there.
__global__ void gru_combine_norm(const float* __restrict__ gcat,
                                 float* __restrict__ slots,
                                 __nv_bfloat16* __restrict__ SH, __nv_bfloat16* __restrict__ SL,
                                 __nv_bfloat16* __restrict__ SNH, __nv_bfloat16* __restrict__ SNL,
                                 const float* __restrict__ snw,
                                 float* __restrict__ out) {
    long r = blockIdx.x;
    int t = threadIdx.x;
    long b3 = r * 3 * DD;
    float4 xr = ((const float4*)(gcat + b3))[t];
    float4 xz = ((const float4*)(gcat + b3 + DD))[t];
    float4 xn = ((const float4*)(gcat + b3 + 2 * DD))[t];
    float4 hr = ((const float4*)(gcat + G_OFF + b3))[t];
    float4 hz = ((const float4*)(gcat + G_OFF + b3 + DD))[t];
    float4 hn = ((const float4*)(gcat + G_OFF + b3 + 2 * DD))[t];
    float4 hprev = ((const float4*)(slots + r * DD))[t];
    float4 o;
    {
        float rg = 1.f / (1.f + __expf(-(xr.x + hr.x)));
        float zg = 1.f / (1.f + __expf(-(xz.x + hz.x)));
        o.x = (1.f - zg) * tanhf(xn.x + rg * hn.x) + zg * hprev.x;
        rg = 1.f / (1.f + __expf(-(xr.y + hr.y)));
        zg = 1.f / (1.f + __expf(-(xz.y + hz.y)));
        o.y = (1.f - zg) * tanhf(xn.y + rg * hn.y) + zg * hprev.y;
        rg = 1.f / (1.f + __expf(-(xr.z + hr.z)));
        zg = 1.f / (1.f + __expf(-(xz.z + hz.z)));
        o.z = (1.f - zg) * tanhf(xn.z + rg * hn.z) + zg * hprev.z;
        rg = 1.f / (1.f + __expf(-(xr.w + hr.w)));
        zg = 1.f / (1.f + __expf(-(xz.w + hz.w)));
        o.w = (1.f - zg) * tanhf(xn.w + rg * hn.w) + zg * hprev.w;
    }
    ((float4*)(slots + r * DD))[t] = o;
    if (out) {
        ((float4*)(out + r * DD))[t] = o;
        return;  // final iteration: hi/lo + norm outputs are not consumed again
    }
    float h0, h1, h2, h3, l0, l1, l2, l3;
    d2(o.x, h0, l0); d2(o.y, h1, l1); d2(o.z, h2, l2); d2(o.w, h3, l3);
    ((uint2*)SH)[r * 256 + t] = make_uint2(pack2(h0, h1), pack2(h2, h3));
    ((uint2*)SL)[r * 256 + t] = make_uint2(pack2(l0, l1), pack2(l2, l3));
    float s = o.x * o.x + o.y * o.y + o.z * o.z + o.w * o.w;
    for (int off = 16; off; off >>= 1) s += __shfl_xor_sync(0xffffffffu, s, off);
    __shared__ float red[8];
    __shared__ float srs;
    if ((t & 31) == 0) red[t >> 5] = s;
    __syncthreads();
    if (t == 0) {
        float tt = 0.f;
#pragma unroll
        for (int i = 0; i < 8; i++) tt += red[i];
        srs = rsqrtf(tt * (1.f / DD) + EPS_F);
    }
    __syncthreads();
    float rs = srs;
    float4 ww = ((const float4*)snw)[t];
    d2(o.x * rs * ww.x, h0, l0); d2(o.y * rs * ww.y, h1, l1);
    d2(o.z * rs * ww.z, h2, l2); d2(o.w * rs * ww.w, h3, l3);
    ((uint2*)SNH)[r * 256 + t] = make_uint2(pack2(h0, h1), pack2(h2, h3));
    ((uint2*)SNL)[r * 256 + t] = make_uint2(pack2(l0, l1), pack2(l2, l3));
}

// ---------------------------------------------------------------------------
// Launch
// ---------------------------------------------------------------------------
extern "C" void kernel_launch(void* const* d_in, const int* in_sizes, int n_in,
                              void* d_out, int out_size)
{
    const float* slots_in = (const float*)d_in[0];
    const float* P        = (const float*)d_in[1];
    const float* Wq       = (const float*)d_in[2];
    const float* Wk       = (const float*)d_in[3];
    const float* Wv       = (const float*)d_in[4];
    const float* wih      = (const float*)d_in[5];
    const float* whh      = (const float*)d_in[6];
    const float* bih      = (const float*)d_in[7];
    const float* bhh      = (const float*)d_in[8];
    const float* snw      = (const float*)d_in[9];
    const float* inw      = (const float*)d_in[10];

    __nv_bfloat16 *pnh, *pnl, *pth, *ptl;
    __nv_bfloat16 *wqh, *wql, *wkh, *wkl, *wvh, *wvl;
    __nv_bfloat16 *wqth, *wqtl, *wkth, *wktl, *wqkth, *wqktl, *wbh, *wbl;
    __nv_bfloat16 *ush, *usl, *awh, *awl, *snh, *snl, *qkh, *qkl, *ath, *atl;
    float *slots, *gcat, *bias2, *partp, *cpart, *rsP;
    cudaGetSymbolAddress((void**)&pnh, g_pnh);     cudaGetSymbolAddress((void**)&pnl, g_pnl);
    cudaGetSymbolAddress((void**)&pth, g_pth);     cudaGetSymbolAddress((void**)&ptl, g_ptl);
    cudaGetSymbolAddress((void**)&wqh, g_wqh);     cudaGetSymbolAddress((void**)&wql, g_wql);
    cudaGetSymbolAddress((void**)&wkh, g_wkh);     cudaGetSymbolAddress((void**)&wkl, g_wkl);
    cudaGetSymbolAddress((void**)&wvh, g_wvh);     cudaGetSymbolAddress((void**)&wvl, g_wvl);
    cudaGetSymbolAddress((void**)&wqth, g_wqth);   cudaGetSymbolAddress((void**)&wqtl, g_wqtl);
    cudaGetSymbolAddress((void**)&wkth, g_wkth);   cudaGetSymbolAddress((void**)&wktl, g_wktl);
    cudaGetSymbolAddress((void**)&wqkth, g_wqkth); cudaGetSymbolAddress((void**)&wqktl, g_wqktl);
    cudaGetSymbolAddress((void**)&wbh, g_wbh);     cudaGetSymbolAddress((void**)&wbl, g_wbl);
    cudaGetSymbolAddress((void**)&ush, g_ush);     cudaGetSymbolAddress((void**)&usl, g_usl);
    cudaGetSymbolAddress((void**)&awh, g_awh);     cudaGetSymbolAddress((void**)&awl, g_awl);
    cudaGetSymbolAddress((void**)&snh, g_snh);     cudaGetSymbolAddress((void**)&snl, g_snl);
    cudaGetSymbolAddress((void**)&qkh, g_qkh);     cudaGetSymbolAddress((void**)&qkl, g_qkl);
    cudaGetSymbolAddress((void**)&ath, g_ath);     cudaGetSymbolAddress((void**)&atl, g_atl);
    cudaGetSymbolAddress((void**)&slots, g_slots);
    cudaGetSymbolAddress((void**)&gcat, g_gcat);
    cudaGetSymbolAddress((void**)&bias2, g_bias2);
    cudaGetSymbolAddress((void**)&partp, g_part);
    cudaGetSymbolAddress((void**)&cpart, g_cpart);
    cudaGetSymbolAddress((void**)&rsP, g_rsP);

    constexpr int SM_128_64 = (128 + 64) * 160 * 3;  // 92160
    constexpr int SM_64_128 = (64 + 128) * 160 * 3;  // 92160
    constexpr int SM_64_64  = (64 + 64) * 160 * 3;   // 61440
    cudaFuncSetAttribute(mma_nt<128,64,3>, cudaFuncAttributeMaxDynamicSharedMemorySize, SM_128_64);
    cudaFuncSetAttribute(mma_nt<128,64,0>, cudaFuncAttributeMaxDynamicSharedMemorySize, SM_128_64);
    cudaFuncSetAttribute(mma_nt<64,128,0>, cudaFuncAttributeMaxDynamicSharedMemorySize, SM_64_128);
    cudaFuncSetAttribute(mma_nt<64,128,1>, cudaFuncAttributeMaxDynamicSharedMemorySize, SM_64_128);
    cudaFuncSetAttribute(mma_nt<64,64,1>,  cudaFuncAttributeMaxDynamicSharedMemorySize, SM_64_64);

    // ---- weight decomposition (single batched launch) ----
    {
        long nW = DD * DD / 4;
        long nG = 3 * DD * DD / 4;
        long tot = 3 * nW + 2 * nG;
        decomp5<<<(int)((tot + 255) / 256), 256>>>(
            Wq, wqh, wql, nW, Wk, wkh, wkl, nW, Wv, wvh, wvl, nW,
            wih, wbh, wbl, nG, whh, wbh + W_OFF, wbl + W_OFF, nG);
    }
    cudaMemcpyAsync(bias2, bih, 3 * DD * sizeof(float), cudaMemcpyDeviceToDevice, 0);
    cudaMemcpyAsync(bias2 + 3 * DD, bhh, 3 * DD * sizeof(float), cudaMemcpyDeviceToDevice, 0);

    // ---- WqkT = (Wq^T Wk)^T ----
    trans_pair2<<<dim3(16, 16, 2), 256>>>(wqh, wql, wqth, wqtl,
                                          wkh, wkl, wkth, wktl, DD, DD);
    mma_nt<64,128,1><<<dim3(DD / 128, DD / 64, 1), 256, SM_64_128>>>(
        wkth, wktl, DD, 0, wqth, wqtl, DD, 0,
        nullptr, wqkth, wqktl, DD, 0, DD, nullptr, 0, 1.f, 1, 0, 0, nullptr);

    // ---- slots init: copy + raw hi/lo + rmsnorm + normed hi/lo (one kernel) ----
    slots_init<<<NB * NS, 256>>>(slots_in, slots, ush + U_OFF, usl + U_OFF,
                                 snh, snl, snw);

    // ---- Pn + PnT (rms pass + fused scale/decomp/transpose pass) ----
    rms_only<<<NB * NM, 256>>>(P, rsP);
    scale_tr<<<dim3(DD / 64, NB * NM / 64), 256>>>(P, rsP, inw, pnh, pnl,
                                                   pth, ptl, (long)NB * NM);

    for (int it = 0; it < 3; it++) {
        // qk = sn @ Wqk
        mma_nt<64,64,1><<<dim3(DD / 64, NB * NS / 64, 1), 256, SM_64_64>>>(
            snh, snl, DD, 0, wqkth, wqktl, DD, 0,
            nullptr, qkh, qkl, DD, 0, DD, nullptr, 0, 1.f, 1, 0, 0, nullptr);

        // scores+softmax fused: writes bf16 hi/lo p [b][k][m] + partials
        mma_nt<128,64,3><<<dim3(1, NM / 128, NB), 256, SM_128_64>>>(
            pnh, pnl, DD, (long)NM * DD, qkh, qkl, DD, (long)NS * DD,
            nullptr, ath, atl, NS, 0, DD, nullptr, 0, SCALE_F, 1, 0, 0, partp);

        // aw partials: split-K x4, BM=128
        mma_nt<128,64,0><<<dim3(1, DD / 128, NB * 4), 256, SM_128_64>>>(
            pth, ptl, (long)NB * NM, NM, ath, atl, NM, (long)NS * NM,
            cpart, nullptr, nullptr, NS, (long)DD * NS, NM / 4, nullptr, 0, 1.f,
            4, 1024, 1024, nullptr);
        reduce_tr<<<dim3(DD / 64, NB), 256>>>(cpart, partp, awh, awl);

        // u = aw @ Wv^T -> packed slot 0 of ush
        mma_nt<64,64,1><<<dim3(DD / 64, NB * NS / 64, 1), 256, SM_64_64>>>(
            awh, awl, DD, 0, wvh, wvl, DD, 0,
            nullptr, ush, usl, DD, 0, DD, nullptr, 0, 1.f, 1, 0, 0, nullptr);

        // GRU gates (z=2, TN=128)
        mma_nt<64,128,0><<<dim3(3 * DD / 128, NB * NS / 64, 2), 256, SM_64_128>>>(
            ush, usl, DD, U_OFF, wbh, wbl, DD, W_OFF,
            gcat, nullptr, nullptr, 3 * DD, G_OFF, DD, bias2, 3 * DD, 1.f, 1, 0, 0, nullptr);

        // pointwise GRU; final iteration writes d_out directly
        gru_combine_norm<<<NB * NS, 256>>>(gcat, slots, ush + U_OFF, usl + U_OFF,
                                           snh, snl, snw,
                                           (it == 2) ? (float*)d_out : nullptr);
    }
}

// round 17
// speedup vs baseline: 1.0335x; 1.0001x over previous
#include <cuda_runtime.h>
#include <cuda_bf16.h>
#include <math.h>
#include <stdint.h>

#define DD 1024
#define NB 8
#define NS 64
#define NM 4096
#define EPS_F 1e-6f
#define SCALE_F 0.03125f

// ---------------------------------------------------------------------------
// Scratch (static device globals)
// ---------------------------------------------------------------------------
__device__ __nv_bfloat16 g_pnh[(long)NB*NM*DD], g_pnl[(long)NB*NM*DD];   // rmsnormed P [bm][d]
__device__ __nv_bfloat16 g_pth[(long)NB*NM*DD], g_ptl[(long)NB*NM*DD];   // PnT [d][b*4096+m]
__device__ __nv_bfloat16 g_wqh[DD*DD],  g_wql[DD*DD];
__device__ __nv_bfloat16 g_wkh[DD*DD],  g_wkl[DD*DD];
__device__ __nv_bfloat16 g_wvh[DD*DD],  g_wvl[DD*DD];
__device__ __nv_bfloat16 g_wqth[DD*DD], g_wqtl[DD*DD];    // WqT
__device__ __nv_bfloat16 g_wkth[DD*DD], g_wktl[DD*DD];    // WkT
__device__ __nv_bfloat16 g_wqkth[DD*DD], g_wqktl[DD*DD];  // (Wq^T Wk)^T
__device__ __nv_bfloat16 g_wbh[2L*3*DD*DD], g_wbl[2L*3*DD*DD];    // gates B: [0]=wih, [1]=whh
__device__ __nv_bfloat16 g_ush[2L*NB*NS*DD], g_usl[2L*NB*NS*DD];  // gates A: [0]=u, [1]=slots raw
__device__ __nv_bfloat16 g_awh[NB*NS*DD], g_awl[NB*NS*DD];        // aw = attn @ Pn (renormed)
__device__ float g_gcat[2L*NB*NS*3*DD];                           // [0]=gx [1]=gh
__device__ float g_bias2[2*3*DD];
__device__ float g_slots[NB*NS*DD];
__device__ float g_rsP[NB*NM];
__device__ __nv_bfloat16 g_snh[NB*NS*DD], g_snl[NB*NS*DD];        // normed slots hi/lo
__device__ __nv_bfloat16 g_qkh[NB*NS*DD], g_qkl[NB*NS*DD];
__device__ float g_part[NB*32*64];
__device__ float g_cpart[64L*DD*NS];                              // split-K partials (16MB)
__device__ __nv_bfloat16 g_ath[(long)NB*NS*NM], g_atl[(long)NB*NS*NM];  // p (softmaxed) [b][k][m]

#define U_OFF  ((long)NB*NS*DD)
#define W_OFF  (3L*DD*DD)
#define G_OFF  ((long)NB*NS*3*DD)

// ---------------------------------------------------------------------------
// Helpers
// ---------------------------------------------------------------------------
__device__ __forceinline__ uint32_t smem_u32(const void* p) {
    uint32_t a;
    asm("{ .reg .u64 t; cvta.to.shared.u64 t, %1; cvt.u32.u64 %0, t; }" : "=r"(a) : "l"(p));
    return a;
}
__device__ __forceinline__ void cpa16(uint32_t dst, const void* src) {
    asm volatile("cp.async.cg.shared.global [%0], [%1], 16;" :: "r"(dst), "l"(src) : "memory");
}
#define CP_COMMIT() asm volatile("cp.async.commit_group;" ::: "memory")
#define CP_WAIT2()  asm volatile("cp.async.wait_group 2;" ::: "memory")
#define CP_WAIT0()  asm volatile("cp.async.wait_group 0;" ::: "memory")

#define LDSM4(r, addr) \
    asm volatile("ldmatrix.sync.aligned.m8n8.x4.shared.b16 {%0,%1,%2,%3}, [%4];" \
        : "=r"((r)[0]), "=r"((r)[1]), "=r"((r)[2]), "=r"((r)[3]) : "r"(addr))

#define MMA4(d, a, b0, b1) \
    asm volatile("mma.sync.aligned.m16n8k16.row.col.f32.bf16.bf16.f32 " \
        "{%0,%1,%2,%3},{%4,%5,%6,%7},{%8,%9},{%0,%1,%2,%3};" \
        : "+f"((d)[0]), "+f"((d)[1]), "+f"((d)[2]), "+f"((d)[3]) \
        : "r"((a)[0]), "r"((a)[1]), "r"((a)[2]), "r"((a)[3]), "r"(b0), "r"(b1))

__device__ __forceinline__ uint32_t pack2(float a, float b) {
    __nv_bfloat162 t = __floats2bfloat162_rn(a, b);
    return *reinterpret_cast<uint32_t*>(&t);
}
__device__ __forceinline__ void d2(float v, float& hi, float& lo) {
    __nv_bfloat16 h = __float2bfloat16_rn(v);
    hi = __bfloat162float(h);
    lo = v - hi;
}

// ---------------------------------------------------------------------------
// Prefetch one BK=32 chunk of A(BM rows) + B(TN rows), hi & lo, into a stage.
// ---------------------------------------------------------------------------
template <int BM, int TN>
__device__ __forceinline__ void prefetch_tiles(
    uint32_t stage,
    const __nv_bfloat16* __restrict__ Ah, const __nv_bfloat16* __restrict__ Al,
    const __nv_bfloat16* __restrict__ Bh, const __nv_bfloat16* __restrict__ Bl,
    long lda, long ldb, int m0, int n0, int k0, int tid)
{
    constexpr int AL_OFF = BM * 80;
    constexpr int BH_OFF = 2 * BM * 80;
#pragma unroll
    for (int i = 0; i < BM / 64; i++) {
        int idx = tid + i * 256;
        int r = idx >> 2, ch = idx & 3;
        long g = (long)(m0 + r) * lda + k0 + ch * 8;
        uint32_t d = stage + (uint32_t)(r * 80 + ch * 16);
        cpa16(d, Ah + g);
        cpa16(d + AL_OFF, Al + g);
    }
#pragma unroll
    for (int i = 0; i < TN / 64; i++) {
        int idx = tid + i * 256;
        int r = idx >> 2, ch = idx & 3;
        long g = (long)(n0 + r) * ldb + k0 + ch * 8;
        uint32_t d = stage + BH_OFF + (uint32_t)(r * 80 + ch * 16);
        cpa16(d, Bh + g);
        cpa16(d + TN * 80, Bl + g);
    }
}

// ---------------------------------------------------------------------------
// bf16x3 NT GEMM via mma.sync, 3-stage cp.async pipeline, 8 warps, 2 CTAs/SM.
// Split-K: blockIdx.z = zb*nsplit + zk.
// EPI: 0 = fp32 out (alpha, bias)   C[m][n]
//      1 = bf16 hi/lo out           C[m][n]
//      3 = softmax over n (TN=64, BM=128, grid.x==1), then bf16 hi/lo
//          TRANSPOSED store Ct[n][m] (un-renormalized) + column partials
// ---------------------------------------------------------------------------
template <int BM, int TN, int EPI>
__global__ __launch_bounds__(256, 2)
void mma_nt(const __nv_bfloat16* __restrict__ Ah, const __nv_bfloat16* __restrict__ Al,
            long lda, long sA,
            const __nv_bfloat16* __restrict__ Bh, const __nv_bfloat16* __restrict__ Bl,
            long ldb, long sB,
            float* __restrict__ Cf,
            __nv_bfloat16* __restrict__ Ch, __nv_bfloat16* __restrict__ Cl,
            long ldc, long sC,
            int Kd, const float* __restrict__ bias, long sBias, float alpha,
            int nsplit, long sAk, long sBk, float* __restrict__ part)
{
    constexpr int WMW = BM / 32;
    constexpr int WNW = 8 / WMW;
    constexpr int WN = TN / WNW;
    constexpr int NF = WN / 8;
    constexpr int NF16 = WN / 16;
    constexpr int AL_OFF = BM * 80;
    constexpr int BH_OFF = 2 * BM * 80;
    constexpr int STAGE = (BM + TN) * 160;

    extern __shared__ char smem[];
    const uint32_t sb = smem_u32(smem);
    const int tid = threadIdx.x, lane = tid & 31, wid = tid >> 5;
    const int wm = wid % WMW, wn = wid / WMW;

    const int m0 = blockIdx.y * BM, n0 = blockIdx.x * TN;
    int zb = blockIdx.z, zk = 0;
    if (nsplit > 1) { zb = blockIdx.z / nsplit; zk = blockIdx.z % nsplit; }
    Ah += (long)zb * sA + (long)zk * sAk;  Al += (long)zb * sA + (long)zk * sAk;
    Bh += (long)zb * sB + (long)zk * sBk;  Bl += (long)zb * sB + (long)zk * sBk;
    if (bias) bias += (long)zb * sBias;

    float acc[2][NF][4];
#pragma unroll
    for (int i = 0; i < 2; i++)
#pragma unroll
        for (int j = 0; j < NF; j++)
#pragma unroll
            for (int k = 0; k < 4; k++) acc[i][j][k] = 0.f;

    const uint32_t aoff = (uint32_t)((wm * 32 + (lane & 15)) * 80 + (lane >> 4) * 16);
    const uint32_t boff = (uint32_t)(BH_OFF + (wn * WN + (lane & 15)) * 80 + (lane >> 4) * 16);

    const int NC = Kd >> 5;
    prefetch_tiles<BM, TN>(sb,             Ah, Al, Bh, Bl, lda, ldb, m0, n0, 0,  tid);
    CP_COMMIT();
    prefetch_tiles<BM, TN>(sb + STAGE,     Ah, Al, Bh, Bl, lda, ldb, m0, n0, 32, tid);
    CP_COMMIT();
    prefetch_tiles<BM, TN>(sb + 2 * STAGE, Ah, Al, Bh, Bl, lda, ldb, m0, n0, 64, tid);
    CP_COMMIT();

    int sidx = 0;
    for (int c = 0; c < NC; c++) {
        CP_WAIT2();
        __syncthreads();
        const uint32_t st = sb + sidx * STAGE;
#pragma unroll
        for (int ks = 0; ks < 2; ks++) {
            const uint32_t ka = st + aoff + ks * 32;
            const uint32_t kb = st + boff + ks * 32;
            uint32_t ah[2][4], al[2][4];
            LDSM4(ah[0], ka);
            LDSM4(ah[1], ka + 16 * 80);
            LDSM4(al[0], ka + AL_OFF);
            LDSM4(al[1], ka + AL_OFF + 16 * 80);
            uint32_t bh[NF16][4], bl[NF16][4];
#pragma unroll
            for (int nf = 0; nf < NF16; nf++) {
                LDSM4(bh[nf], kb + nf * 16 * 80);
                LDSM4(bl[nf], kb + TN * 80 + nf * 16 * 80);
            }
#pragma unroll
            for (int mf = 0; mf < 2; mf++)
#pragma unroll
                for (int nf = 0; nf < NF16; nf++) {
                    MMA4(acc[mf][2*nf],   ah[mf], bh[nf][0], bh[nf][2]);
                    MMA4(acc[mf][2*nf+1], ah[mf], bh[nf][1], bh[nf][3]);
                    MMA4(acc[mf][2*nf],   ah[mf], bl[nf][0], bl[nf][2]);
                    MMA4(acc[mf][2*nf+1], ah[mf], bl[nf][1], bl[nf][3]);
                    MMA4(acc[mf][2*nf],   al[mf], bh[nf][0], bh[nf][2]);
                    MMA4(acc[mf][2*nf+1], al[mf], bh[nf][1], bh[nf][3]);
                }
        }
        __syncthreads();
        if (c + 3 < NC)
            prefetch_tiles<BM, TN>(sb + sidx * STAGE, Ah, Al, Bh, Bl,
                                   lda, ldb, m0, n0, (c + 3) * 32, tid);
        CP_COMMIT();
        sidx = (sidx == 2) ? 0 : sidx + 1;
    }
    CP_WAIT0();
    __syncthreads();

    // ---- epilogue ----
    const int rbase = m0 + wm * 32;
    const int cbase = n0 + wn * WN;
    if (EPI == 0) {
        float* C = Cf + (long)blockIdx.z * sC;
#pragma unroll
        for (int mf = 0; mf < 2; mf++) {
            int row = rbase + mf * 16 + (lane >> 2);
#pragma unroll
            for (int nf = 0; nf < NF; nf++) {
                int col = cbase + nf * 8 + (lane & 3) * 2;
                float b0 = bias ? bias[col] : 0.f, b1 = bias ? bias[col + 1] : 0.f;
                float2 v0 = make_float2(acc[mf][nf][0] * alpha + b0,
                                        acc[mf][nf][1] * alpha + b1);
                float2 v1 = make_float2(acc[mf][nf][2] * alpha + b0,
                                        acc[mf][nf][3] * alpha + b1);
                *(float2*)(C + (long)row * ldc + col) = v0;
                *(float2*)(C + (long)(row + 8) * ldc + col) = v1;
            }
        }
    } else if (EPI == 1) {
        __nv_bfloat16* CH = Ch + (long)blockIdx.z * sC;
        __nv_bfloat16* CL = Cl + (long)blockIdx.z * sC;
#pragma unroll
        for (int mf = 0; mf < 2; mf++) {
            int row = rbase + mf * 16 + (lane >> 2);
#pragma unroll
            for (int nf = 0; nf < NF; nf++) {
                int col = cbase + nf * 8 + (lane & 3) * 2;
                float h0, l0, h1, l1;
                d2(acc[mf][nf][0] * alpha, h0, l0);
                d2(acc[mf][nf][1] * alpha, h1, l1);
                *(uint32_t*)(CH + (long)row * ldc + col) = pack2(h0, h1);
                *(uint32_t*)(CL + (long)row * ldc + col) = pack2(l0, l1);
                d2(acc[mf][nf][2] * alpha, h0, l0);
                d2(acc[mf][nf][3] * alpha, h1, l1);
                *(uint32_t*)(CH + (long)(row + 8) * ldc + col) = pack2(h0, h1);
                *(uint32_t*)(CL + (long)(row + 8) * ldc + col) = pack2(l0, l1);
            }
        }
    } else {
        // EPI==3: in-CTA softmax over full n (TN==NS), bf16 hi/lo transposed
        // store (un-renormalized) + per-block column partial sums.
        float* ts = reinterpret_cast<float*>(smem);
        const int rl = wm * 32;
        const int cl = wn * WN;
#pragma unroll
        for (int mf = 0; mf < 2; mf++) {
            int row = rl + mf * 16 + (lane >> 2);
#pragma unroll
            for (int nf = 0; nf < NF; nf++) {
                int col = cl + nf * 8 + (lane & 3) * 2;
                ts[(row)     * 65 + col]     = acc[mf][nf][0] * alpha;
                ts[(row)     * 65 + col + 1] = acc[mf][nf][1] * alpha;
                ts[(row + 8) * 65 + col]     = acc[mf][nf][2] * alpha;
                ts[(row + 8) * 65 + col + 1] = acc[mf][nf][3] * alpha;
            }
        }
        __syncthreads();
        {
            int row = tid >> 1, half = tid & 1;
            float* p = ts + row * 65 + half * 32;
            float mx = -INFINITY;
#pragma unroll
            for (int i = 0; i < 32; i++) mx = fmaxf(mx, p[i]);
            mx = fmaxf(mx, __shfl_xor_sync(0xffffffffu, mx, 1));
            float sum = 0.f;
            float e[32];
#pragma unroll
            for (int i = 0; i < 32; i++) { e[i] = __expf(p[i] - mx); sum += e[i]; }
            sum += __shfl_xor_sync(0xffffffffu, sum, 1);
            float inv = 1.f / sum;
#pragma unroll
            for (int i = 0; i < 32; i++) p[i] = e[i] * inv;
        }
        __syncthreads();
        if (tid < 64) {
            float s = 0.f;
#pragma unroll 8
            for (int r = 0; r < 128; r++) s += ts[r * 65 + tid];
            part[((long)blockIdx.z * gridDim.y + blockIdx.y) * 64 + tid] = s;
        }
#pragma unroll
        for (int j = 0; j < 16; j++) {
            int u = tid + j * 256;
            int k = u >> 6, m2 = (u & 63) * 2;
            float v0 = ts[(m2 + 0) * 65 + k];
            float v1 = ts[(m2 + 1) * 65 + k];
            float h0, l0, h1, l1;
            d2(v0, h0, l0); d2(v1, h1, l1);
            long o = ((long)blockIdx.z * 64 + k) * NM + m0 + m2;
            *(uint32_t*)(Ch + o) = pack2(h0, h1);
            *(uint32_t*)(Cl + o) = pack2(l0, l1);
        }
    }
}

// ---------------------------------------------------------------------------
// Elementwise / layout kernels
// ---------------------------------------------------------------------------
__global__ void rms_only(const float* __restrict__ X, float* __restrict__ rs) {
    long r = blockIdx.x;
    float4 v = ((const float4*)(X + r * DD))[threadIdx.x];
    float s = v.x * v.x + v.y * v.y + v.z * v.z + v.w * v.w;
    for (int o = 16; o; o >>= 1) s += __shfl_xor_sync(0xffffffffu, s, o);
    __shared__ float red[8];
    if ((threadIdx.x & 31) == 0) red[threadIdx.x >> 5] = s;
    __syncthreads();
    if (threadIdx.x == 0) {
        float t = 0.f;
#pragma unroll
        for (int i = 0; i < 8; i++) t += red[i];
        rs[r] = rsqrtf(t * (1.f / DD) + EPS_F);
    }
}

// fused scale + decomp + dual-layout write (Pn and PnT) per 64m x 64d tile
__global__ void scale_tr(const float* __restrict__ P, const float* __restrict__ rs,
                         const float* __restrict__ w,
                         __nv_bfloat16* __restrict__ H, __nv_bfloat16* __restrict__ L,
                         __nv_bfloat16* __restrict__ HT, __nv_bfloat16* __restrict__ LT,
                         long R) {
    __shared__ uint16_t th[64][66], tl[64][66];
    int d0 = blockIdx.x * 64;
    long m0 = (long)blockIdx.y * 64;
    int tid = threadIdx.x;
#pragma unroll
    for (int j = 0; j < 4; j++) {
        int u = tid + j * 256;
        int row = u >> 4, c4 = (u & 15) * 4;
        long gi = (m0 + row) * DD + d0 + c4;
        float4 v = *(const float4*)(P + gi);
        float rsv = rs[m0 + row];
        float h0, h1, h2, h3, l0, l1, l2, l3;
        d2(v.x * rsv * w[d0 + c4 + 0], h0, l0);
        d2(v.y * rsv * w[d0 + c4 + 1], h1, l1);
        d2(v.z * rsv * w[d0 + c4 + 2], h2, l2);
        d2(v.w * rsv * w[d0 + c4 + 3], h3, l3);
        *(uint2*)(H + gi) = make_uint2(pack2(h0, h1), pack2(h2, h3));
        *(uint2*)(L + gi) = make_uint2(pack2(l0, l1), pack2(l2, l3));
        uint16_t* hp = (uint16_t*)&th[row][c4];
        uint16_t* lp = (uint16_t*)&tl[row][c4];
        __nv_bfloat16 b;
        b = __float2bfloat16_rn(h0); hp[0] = *(uint16_t*)&b;
        b = __float2bfloat16_rn(h1); hp[1] = *(uint16_t*)&b;
        b = __float2bfloat16_rn(h2); hp[2] = *(uint16_t*)&b;
        b = __float2bfloat16_rn(h3); hp[3] = *(uint16_t*)&b;
        b = __float2bfloat16_rn(l0); lp[0] = *(uint16_t*)&b;
        b = __float2bfloat16_rn(l1); lp[1] = *(uint16_t*)&b;
        b = __float2bfloat16_rn(l2); lp[2] = *(uint16_t*)&b;
        b = __float2bfloat16_rn(l3); lp[3] = *(uint16_t*)&b;
    }
    __syncthreads();
#pragma unroll
    for (int j = 0; j < 8; j++) {
        int u = tid + j * 256;
        int d = u >> 5, m2 = (u & 31) * 2;
        uint32_t vh = (uint32_t)th[m2][d] | ((uint32_t)th[m2 + 1][d] << 16);
        uint32_t vl = (uint32_t)tl[m2][d] | ((uint32_t)tl[m2 + 1][d] << 16);
        long o = (long)(d0 + d) * R + m0 + m2;
        *(uint32_t*)(HT + o) = vh;
        *(uint32_t*)(LT + o) = vl;
    }
}

// slots init: copy fp32, raw hi/lo, fused rmsnorm + normed hi/lo (1 block/row)
__global__ void slots_init(const float* __restrict__ Sin, float* __restrict__ S,
                           __nv_bfloat16* __restrict__ SH, __nv_bfloat16* __restrict__ SL,
                           __nv_bfloat16* __restrict__ SNH, __nv_bfloat16* __restrict__ SNL,
                           const float* __restrict__ snw) {
    long r = blockIdx.x;
    int t = threadIdx.x;
    float4 v = ((const float4*)(Sin + r * DD))[t];
    ((float4*)(S + r * DD))[t] = v;
    float h0, h1, h2, h3, l0, l1, l2, l3;
    d2(v.x, h0, l0); d2(v.y, h1, l1); d2(v.z, h2, l2); d2(v.w, h3, l3);
    ((uint2*)SH)[r * 256 + t] = make_uint2(pack2(h0, h1), pack2(h2, h3));
    ((uint2*)SL)[r * 256 + t] = make_uint2(pack2(l0, l1), pack2(l2, l3));
    float s = v.x * v.x + v.y * v.y + v.z * v.z + v.w * v.w;
    for (int o = 16; o; o >>= 1) s += __shfl_xor_sync(0xffffffffu, s, o);
    __shared__ float red[8];
    __shared__ float srs;
    if ((t & 31) == 0) red[t >> 5] = s;
    __syncthreads();
    if (t == 0) {
        float tt = 0.f;
#pragma unroll
        for (int i = 0; i < 8; i++) tt += red[i];
        srs = rsqrtf(tt * (1.f / DD) + EPS_F);
    }
    __syncthreads();
    float rs = srs;
    float4 ww = ((const float4*)snw)[t];
    d2(v.x * rs * ww.x, h0, l0); d2(v.y * rs * ww.y, h1, l1);
    d2(v.z * rs * ww.z, h2, l2); d2(v.w * rs * ww.w, h3, l3);
    ((uint2*)SNH)[r * 256 + t] = make_uint2(pack2(h0, h1), pack2(h2, h3));
    ((uint2*)SNL)[r * 256 + t] = make_uint2(pack2(l0, l1), pack2(l2, l3));
}

// batched hi/lo decomposition over 5 weight tensors (one launch)
__global__ void decomp5(const float* __restrict__ s0, __nv_bfloat16* d0h, __nv_bfloat16* d0l, long n0,
                        const float* __restrict__ s1, __nv_bfloat16* d1h, __nv_bfloat16* d1l, long n1,
                        const float* __restrict__ s2, __nv_bfloat16* d2h_, __nv_bfloat16* d2l, long n2,
                        const float* __restrict__ s3, __nv_bfloat16* d3h, __nv_bfloat16* d3l, long n3,
                        const float* __restrict__ s4, __nv_bfloat16* d4h, __nv_bfloat16* d4l, long n4c) {
    long i = (long)blockIdx.x * blockDim.x + threadIdx.x;
    const float* src; __nv_bfloat16 *dh, *dl;
    if (i < n0)      { src = s0; dh = d0h; dl = d0l; }
    else if ((i -= n0) < n1) { src = s1; dh = d1h; dl = d1l; }
    else if ((i -= n1) < n2) { src = s2; dh = d2h_; dl = d2l; }
    else if ((i -= n2) < n3) { src = s3; dh = d3h; dl = d3l; }
    else if ((i -= n3) < n4c) { src = s4; dh = d4h; dl = d4l; }
    else return;
    float4 v = ((const float4*)src)[i];
    float h0, h1, h2, h3, l0, l1, l2, l3;
    d2(v.x, h0, l0); d2(v.y, h1, l1); d2(v.z, h2, l2); d2(v.w, h3, l3);
    ((uint2*)dh)[i] = make_uint2(pack2(h0, h1), pack2(h2, h3));
    ((uint2*)dl)[i] = make_uint2(pack2(l0, l1), pack2(l2, l3));
}

// sum 4 split-K fp32 slices, decompose hi/lo
__global__ void sum4_dec(const float* __restrict__ cp,
                         __nv_bfloat16* __restrict__ H, __nv_bfloat16* __restrict__ L,
                         long n4) {
    long i = (long)blockIdx.x * blockDim.x + threadIdx.x;
    if (i >= n4) return;
    float4 a = ((const float4*)cp)[i];
    float4 b = ((const float4*)cp)[i + n4];
    float4 c = ((const float4*)cp)[i + 2 * n4];
    float4 d = ((const float4*)cp)[i + 3 * n4];
    a.x += b.x + c.x + d.x;
    a.y += b.y + c.y + d.y;
    a.z += b.z + c.z + d.z;
    a.w += b.w + c.w + d.w;
    float h0, h1, h2, h3, l0, l1, l2, l3;
    d2(a.x, h0, l0); d2(a.y, h1, l1); d2(a.z, h2, l2); d2(a.w, h3, l3);
    ((uint2*)H)[i] = make_uint2(pack2(h0, h1), pack2(h2, h3));
    ((uint2*)L)[i] = make_uint2(pack2(l0, l1), pack2(l2, l3));
}

// 64x64-tile transpose of TWO bf16 hi/lo pairs (z selects pair): [R][C]->[C][R]
__global__ void trans_pair2(const __nv_bfloat16* __restrict__ H0, const __nv_bfloat16* __restrict__ L0,
                            __nv_bfloat16* __restrict__ HT0, __nv_bfloat16* __restrict__ LT0,
                            const __nv_bfloat16* __restrict__ H1, const __nv_bfloat16* __restrict__ L1,
                            __nv_bfloat16* __restrict__ HT1, __nv_bfloat16* __restrict__ LT1,
                            int C, long R) {
    __shared__ uint16_t t[64][66];
    const __nv_bfloat16* H = blockIdx.z ? H1 : H0;
    const __nv_bfloat16* L = blockIdx.z ? L1 : L0;
    __nv_bfloat16* HT = blockIdx.z ? HT1 : HT0;
    __nv_bfloat16* LT = blockIdx.z ? LT1 : LT0;
    long r0 = (long)blockIdx.y * 64;
    int c0 = blockIdx.x * 64;
    int tid = threadIdx.x;
#pragma unroll
    for (int pass = 0; pass < 2; pass++) {
        const __nv_bfloat16* src = pass ? L : H;
        __nv_bfloat16* dst = pass ? LT : HT;
#pragma unroll
        for (int j = 0; j < 8; j++) {
            int u = tid + j * 256;
            int r = u >> 5, c2 = (u & 31) * 2;
            uint32_t v = *(const uint32_t*)(src + (r0 + r) * C + c0 + c2);
            t[r][c2] = (uint16_t)(v & 0xffff);
            t[r][c2 + 1] = (uint16_t)(v >> 16);
        }
        __syncthreads();
#pragma unroll
        for (int j = 0; j < 8; j++) {
            int u = tid + j * 256;
            int c = u >> 5, r2 = (u & 31) * 2;
            uint32_t v = (uint32_t)t[r2][c] | ((uint32_t)t[r2 + 1][c] << 16);
            *(uint32_t*)(dst + (long)(c0 + c) * R + r0 + r2) = v;
        }
        __syncthreads();
    }
}

// sum 4 split-K partials [d][k], apply per-k renorm inv, transpose -> [k][d],
// decompose hi/lo.
__global__ void reduce_tr(const float* __restrict__ cp, const float* __restrict__ part,
                          __nv_bfloat16* __restrict__ UH, __nv_bfloat16* __restrict__ UL) {
    __shared__ float t[64 * 65];
    __shared__ float inv[64];
    int d0 = blockIdx.x * 64, b = blockIdx.y;
    int tid = threadIdx.x;
    if (tid < 64) {
        float s = 0.f;
#pragma unroll
        for (int j = 0; j < 32; j++) s += part[(b * 32 + j) * 64 + tid];
        inv[tid] = 1.f / (s + EPS_F);
    }
    const float* base = cp + (long)(b * 4) * DD * NS + (long)d0 * NS;
#pragma unroll
    for (int j = 0; j < 4; j++) {
        int u = tid + j * 256;
        int du = u >> 4, kq = (u & 15);
        float4 acc = ((const float4*)(base + (long)du * NS))[kq];
#pragma unroll
        for (int sl = 1; sl < 4; sl++) {
            float4 v = ((const float4*)(base + (long)sl * DD * NS + (long)du * NS))[kq];
            acc.x += v.x; acc.y += v.y; acc.z += v.z; acc.w += v.w;
        }
        t[du * 65 + kq * 4 + 0] = acc.x;
        t[du * 65 + kq * 4 + 1] = acc.y;
        t[du * 65 + kq * 4 + 2] = acc.z;
        t[du * 65 + kq * 4 + 3] = acc.w;
    }
    __syncthreads();
#pragma unroll
    for (int j = 0; j < 8; j++) {
        int u = tid + j * 256;
        int k = u >> 5, d2i = (u & 31) * 2;
        float iv = inv[k];
        float v0 = t[(d2i + 0) * 65 + k] * iv;
        float v1 = t[(d2i + 1) * 65 + k] * iv;
        float h0, l0, h1, l1;
        d2(v0, h0, l0); d2(v1, h1, l1);
        long o = ((long)b * NS + k) * DD + d0 + d2i;
        *(uint32_t*)(UH + o) = pack2(h0, h1);
        *(uint32_t*)(UL + o) = pack2(l0, l1);
    }
}

// GRU pointwise + raw hi/lo + fused rmsnorm/decomp of new slots (1 block/row).
// On the final iteration `out` is non-null: result is also written there.
__global__ void gru_combine_norm(const float* __restrict__ gcat,
                                 float* __restrict__ slots,
                                 __nv_bfloat16* __restrict__ SH, __nv_bfloat16* __restrict__ SL,
                                 __nv_bfloat16* __restrict__ SNH, __nv_bfloat16* __restrict__ SNL,
                                 const float* __restrict__ snw,
                                 float* __restrict__ out) {
    long r = blockIdx.x;
    int t = threadIdx.x;
    long b3 = r * 3 * DD;
    float4 xr = ((const float4*)(gcat + b3))[t];
    float4 xz = ((const float4*)(gcat + b3 + DD))[t];
    float4 xn = ((const float4*)(gcat + b3 + 2 * DD))[t];
    float4 hr = ((const float4*)(gcat + G_OFF + b3))[t];
    float4 hz = ((const float4*)(gcat + G_OFF + b3 + DD))[t];
    float4 hn = ((const float4*)(gcat + G_OFF + b3 + 2 * DD))[t];
    float4 hprev = ((const float4*)(slots + r * DD))[t];
    float4 o;
    {
        float rg = 1.f / (1.f + __expf(-(xr.x + hr.x)));
        float zg = 1.f / (1.f + __expf(-(xz.x + hz.x)));
        o.x = (1.f - zg) * tanhf(xn.x + rg * hn.x) + zg * hprev.x;
        rg = 1.f / (1.f + __expf(-(xr.y + hr.y)));
        zg = 1.f / (1.f + __expf(-(xz.y + hz.y)));
        o.y = (1.f - zg) * tanhf(xn.y + rg * hn.y) + zg * hprev.y;
        rg = 1.f / (1.f + __expf(-(xr.z + hr.z)));
        zg = 1.f / (1.f + __expf(-(xz.z + hz.z)));
        o.z = (1.f - zg) * tanhf(xn.z + rg * hn.z) + zg * hprev.z;
        rg = 1.f / (1.f + __expf(-(xr.w + hr.w)));
        zg = 1.f / (1.f + __expf(-(xz.w + hz.w)));
        o.w = (1.f - zg) * tanhf(xn.w + rg * hn.w) + zg * hprev.w;
    }
    ((float4*)(slots + r * DD))[t] = o;
    if (out) {
        ((float4*)(out + r * DD))[t] = o;
        return;  // final iteration: hi/lo + norm outputs are not consumed again
    }
    float h0, h1, h2, h3, l0, l1, l2, l3;
    d2(o.x, h0, l0); d2(o.y, h1, l1); d2(o.z, h2, l2); d2(o.w, h3, l3);
    ((uint2*)SH)[r * 256 + t] = make_uint2(pack2(h0, h1), pack2(h2, h3));
    ((uint2*)SL)[r * 256 + t] = make_uint2(pack2(l0, l1), pack2(l2, l3));
    float s = o.x * o.x + o.y * o.y + o.z * o.z + o.w * o.w;
    for (int off = 16; off; off >>= 1) s += __shfl_xor_sync(0xffffffffu, s, off);
    __shared__ float red[8];
    __shared__ float srs;
    if ((t & 31) == 0) red[t >> 5] = s;
    __syncthreads();
    if (t == 0) {
        float tt = 0.f;
#pragma unroll
        for (int i = 0; i < 8; i++) tt += red[i];
        srs = rsqrtf(tt * (1.f / DD) + EPS_F);
    }
    __syncthreads();
    float rs = srs;
    float4 ww = ((const float4*)snw)[t];
    d2(o.x * rs * ww.x, h0, l0); d2(o.y * rs * ww.y, h1, l1);
    d2(o.z * rs * ww.z, h2, l2); d2(o.w * rs * ww.w, h3, l3);
    ((uint2*)SNH)[r * 256 + t] = make_uint2(pack2(h0, h1), pack2(h2, h3));
    ((uint2*)SNL)[r * 256 + t] = make_uint2(pack2(l0, l1), pack2(l2, l3));
}

// ---------------------------------------------------------------------------
// Launch
// ---------------------------------------------------------------------------
extern "C" void kernel_launch(void* const* d_in, const int* in_sizes, int n_in,
                              void* d_out, int out_size)
{
    const float* slots_in = (const float*)d_in[0];
    const float* P        = (const float*)d_in[1];
    const float* Wq       = (const float*)d_in[2];
    const float* Wk       = (const float*)d_in[3];
    const float* Wv       = (const float*)d_in[4];
    const float* wih      = (const float*)d_in[5];
    const float* whh      = (const float*)d_in[6];
    const float* bih      = (const float*)d_in[7];
    const float* bhh      = (const float*)d_in[8];
    const float* snw      = (const float*)d_in[9];
    const float* inw      = (const float*)d_in[10];

    __nv_bfloat16 *pnh, *pnl, *pth, *ptl;
    __nv_bfloat16 *wqh, *wql, *wkh, *wkl, *wvh, *wvl;
    __nv_bfloat16 *wqth, *wqtl, *wkth, *wktl, *wqkth, *wqktl, *wbh, *wbl;
    __nv_bfloat16 *ush, *usl, *awh, *awl, *snh, *snl, *qkh, *qkl, *ath, *atl;
    float *slots, *gcat, *bias2, *partp, *cpart, *rsP;
    cudaGetSymbolAddress((void**)&pnh, g_pnh);     cudaGetSymbolAddress((void**)&pnl, g_pnl);
    cudaGetSymbolAddress((void**)&pth, g_pth);     cudaGetSymbolAddress((void**)&ptl, g_ptl);
    cudaGetSymbolAddress((void**)&wqh, g_wqh);     cudaGetSymbolAddress((void**)&wql, g_wql);
    cudaGetSymbolAddress((void**)&wkh, g_wkh);     cudaGetSymbolAddress((void**)&wkl, g_wkl);
    cudaGetSymbolAddress((void**)&wvh, g_wvh);     cudaGetSymbolAddress((void**)&wvl, g_wvl);
    cudaGetSymbolAddress((void**)&wqth, g_wqth);   cudaGetSymbolAddress((void**)&wqtl, g_wqtl);
    cudaGetSymbolAddress((void**)&wkth, g_wkth);   cudaGetSymbolAddress((void**)&wktl, g_wktl);
    cudaGetSymbolAddress((void**)&wqkth, g_wqkth); cudaGetSymbolAddress((void**)&wqktl, g_wqktl);
    cudaGetSymbolAddress((void**)&wbh, g_wbh);     cudaGetSymbolAddress((void**)&wbl, g_wbl);
    cudaGetSymbolAddress((void**)&ush, g_ush);     cudaGetSymbolAddress((void**)&usl, g_usl);
    cudaGetSymbolAddress((void**)&awh, g_awh);     cudaGetSymbolAddress((void**)&awl, g_awl);
    cudaGetSymbolAddress((void**)&snh, g_snh);     cudaGetSymbolAddress((void**)&snl, g_snl);
    cudaGetSymbolAddress((void**)&qkh, g_qkh);     cudaGetSymbolAddress((void**)&qkl, g_qkl);
    cudaGetSymbolAddress((void**)&ath, g_ath);     cudaGetSymbolAddress((void**)&atl, g_atl);
    cudaGetSymbolAddress((void**)&slots, g_slots);
    cudaGetSymbolAddress((void**)&gcat, g_gcat);
    cudaGetSymbolAddress((void**)&bias2, g_bias2);
    cudaGetSymbolAddress((void**)&partp, g_part);
    cudaGetSymbolAddress((void**)&cpart, g_cpart);
    cudaGetSymbolAddress((void**)&rsP, g_rsP);

    constexpr int SM_128_64 = (128 + 64) * 160 * 3;  // 92160
    constexpr int SM_64_128 = (64 + 128) * 160 * 3;  // 92160
    constexpr int SM_64_64  = (64 + 64) * 160 * 3;   // 61440
    cudaFuncSetAttribute(mma_nt<128,64,3>, cudaFuncAttributeMaxDynamicSharedMemorySize, SM_128_64);
    cudaFuncSetAttribute(mma_nt<128,64,0>, cudaFuncAttributeMaxDynamicSharedMemorySize, SM_128_64);
    cudaFuncSetAttribute(mma_nt<64,128,0>, cudaFuncAttributeMaxDynamicSharedMemorySize, SM_64_128);
    cudaFuncSetAttribute(mma_nt<64,64,0>,  cudaFuncAttributeMaxDynamicSharedMemorySize, SM_64_64);

    // ---- weight decomposition (single batched launch) ----
    {
        long nW = DD * DD / 4;
        long nG = 3 * DD * DD / 4;
        long tot = 3 * nW + 2 * nG;
        decomp5<<<(int)((tot + 255) / 256), 256>>>(
            Wq, wqh, wql, nW, Wk, wkh, wkl, nW, Wv, wvh, wvl, nW,
            wih, wbh, wbl, nG, whh, wbh + W_OFF, wbl + W_OFF, nG);
    }
    cudaMemcpyAsync(bias2, bih, 3 * DD * sizeof(float), cudaMemcpyDeviceToDevice, 0);
    cudaMemcpyAsync(bias2 + 3 * DD, bhh, 3 * DD * sizeof(float), cudaMemcpyDeviceToDevice, 0);

    // ---- WqkT = (Wq^T Wk)^T (split-K x4: fp32 partials + reduce) ----
    trans_pair2<<<dim3(16, 16, 2), 256>>>(wqh, wql, wqth, wqtl,
                                          wkh, wkl, wkth, wktl, DD, DD);
    mma_nt<64,128,0><<<dim3(DD / 128, DD / 64, 4), 256, SM_64_128>>>(
        wkth, wktl, DD, 0, wqth, wqtl, DD, 0,
        cpart, nullptr, nullptr, DD, (long)DD * DD, DD / 4, nullptr, 0, 1.f,
        4, DD / 4, DD / 4, nullptr);
    sum4_dec<<<DD * DD / 4 / 256, 256>>>(cpart, wqkth, wqktl, DD * DD / 4);

    // ---- slots init: copy + raw hi/lo + rmsnorm + normed hi/lo (one kernel) ----
    slots_init<<<NB * NS, 256>>>(slots_in, slots, ush + U_OFF, usl + U_OFF,
                                 snh, snl, snw);

    // ---- Pn + PnT (rms pass + fused scale/decomp/transpose pass) ----
    rms_only<<<NB * NM, 256>>>(P, rsP);
    scale_tr<<<dim3(DD / 64, NB * NM / 64), 256>>>(P, rsP, inw, pnh, pnl,
                                                   pth, ptl, (long)NB * NM);

    for (int it = 0; it < 3; it++) {
        // qk = sn @ Wqk  (split-K x4: fp32 partials + reduce)
        mma_nt<64,64,0><<<dim3(DD / 64, NB * NS / 64, 4), 256, SM_64_64>>>(
            snh, snl, DD, 0, wqkth, wqktl, DD, 0,
            cpart, nullptr, nullptr, DD, (long)NB * NS * DD, DD / 4, nullptr, 0, 1.f,
            4, DD / 4, DD / 4, nullptr);
        sum4_dec<<<NB * NS * DD / 4 / 256, 256>>>(cpart, qkh, qkl, NB * NS * DD / 4);

        // scores+softmax fused: writes bf16 hi/lo p [b][k][m] + partials
        mma_nt<128,64,3><<<dim3(1, NM / 128, NB), 256, SM_128_64>>>(
            pnh, pnl, DD, (long)NM * DD, qkh, qkl, DD, (long)NS * DD,
            nullptr, ath, atl, NS, 0, DD, nullptr, 0, SCALE_F, 1, 0, 0, partp);

        // aw partials: split-K x4, BM=128
        mma_nt<128,64,0><<<dim3(1, DD / 128, NB * 4), 256, SM_128_64>>>(
            pth, ptl, (long)NB * NM, NM, ath, atl, NM, (long)NS * NM,
            cpart, nullptr, nullptr, NS, (long)DD * NS, NM / 4, nullptr, 0, 1.f,
            4, 1024, 1024, nullptr);
        reduce_tr<<<dim3(DD / 64, NB), 256>>>(cpart, partp, awh, awl);

        // u = aw @ Wv^T (split-K x4) -> packed slot 0 of ush
        mma_nt<64,64,0><<<dim3(DD / 64, NB * NS / 64, 4), 256, SM_64_64>>>(
            awh, awl, DD, 0, wvh, wvl, DD, 0,
            cpart, nullptr, nullptr, DD, (long)NB * NS * DD, DD / 4, nullptr, 0, 1.f,
            4, DD / 4, DD / 4, nullptr);
        sum4_dec<<<NB * NS * DD / 4 / 256, 256>>>(cpart, ush, usl, NB * NS * DD / 4);

        // GRU gates (z=2, TN=128)
        mma_nt<64,128,0><<<dim3(3 * DD / 128, NB * NS / 64, 2), 256, SM_64_128>>>(
            ush, usl, DD, U_OFF, wbh, wbl, DD, W_OFF,
            gcat, nullptr, nullptr, 3 * DD, G_OFF, DD, bias2, 3 * DD, 1.f, 1, 0, 0, nullptr);

        // pointwise GRU; final iteration writes d_out directly
        gru_combine_norm<<<NB * NS, 256>>>(gcat, slots, ush + U_OFF, usl + U_OFF,
                                           snh, snl, snw,
                                           (it == 2) ? (float*)d_out : nullptr);
    }
}